// round 10
// baseline (speedup 1.0000x reference)
#include <cuda_runtime.h>
#include <math.h>

// GATv2 x3 + pooling: CSR + offset-softmax fused edge passes.
// Layer 1: on-the-fly 8->128 transform (32B broadcast gathers, no linear).
// Layers 2/3: ILP4 fused pass + dual register-tiled linears. SMEM pooling.
namespace {
constexpr int NN = 50000;
constexpr int NE = 800000;
constexpr int ET = NE + NN;
constexpr int NG = 16;
constexpr int TB = 256;
}

// ---------------- scratch ---------------------------------------------------
__device__ __align__(16) float g_xl[(size_t)NN * 128];
__device__ __align__(16) float g_xr[(size_t)NN * 128];
__device__ __align__(16) float g_h[(size_t)NN * 128];
__device__ int g_deg[NN];            // zero-initialized at load; re-zeroed in fill
__device__ int g_rowptr[NN + 1];
__device__ int g_cur[NN];
__device__ int g_csrc[ET];
__device__ float g_psum[NG * 32];
__device__ float g_pmax[NG * 32];
__device__ float g_cntf[NG];

__device__ __forceinline__ void atomicMaxF(float* a, float v) {
    if (v >= 0.f) atomicMax((int*)a, __float_as_int(v));
    else          atomicMin((unsigned int*)a, __float_as_uint(v));
}

// ---------------- CSR build (deg counted from 0; +1 self loop in scan) ------
__global__ void deg_count_kernel(const int* __restrict__ ei) {
    int e = blockIdx.x * blockDim.x + threadIdx.x;
    if (e < NE) atomicAdd(&g_deg[ei[NE + e]], 1);
}
__global__ void scan_kernel() {
    __shared__ int part[1024];
    const int tid = threadIdx.x;
    const int chunk = (NN + 1023) / 1024;
    const int beg = tid * chunk;
    const int end = min(beg + chunk, NN);
    int s = 0;
    for (int i = beg; i < end; i++) s += g_deg[i] + 1;   // +1 = self loop
    part[tid] = s;
    __syncthreads();
    if (tid == 0) {
        int run = 0;
        for (int i = 0; i < 1024; i++) { int t = part[i]; part[i] = run; run += t; }
    }
    __syncthreads();
    int run = part[tid];
    for (int i = beg; i < end; i++) {
        g_rowptr[i] = run;
        g_cur[i] = run;
        run += g_deg[i] + 1;
    }
    if (tid == 0) g_rowptr[NN] = ET;
}
__global__ void fill_kernel(const int* __restrict__ ei) {
    int e = blockIdx.x * blockDim.x + threadIdx.x;
    if (e < NN) g_deg[e] = 0;        // re-zero for next replay (scan already done)
    if (e >= ET) return;
    int src, dst;
    if (e < NE) { src = ei[e]; dst = ei[NE + e]; }
    else        { src = e - NE; dst = src; }
    int pos = atomicAdd(&g_cur[dst], 1);
    g_csrc[pos] = src;
}

// ---------------- layer-1 fused: 8-dim input, on-the-fly transform ----------
// warp per dst node; lane owns output channels [lane*4, lane*4+4).
// xl[src] computed per gather from 32B broadcast x row; offset softmax.
__global__ __launch_bounds__(256)
void gat_fused_l1_kernel(const float* __restrict__ X,
                         const float* __restrict__ Wl, const float* __restrict__ Bl,
                         const float* __restrict__ Wr, const float* __restrict__ Br,
                         const float* __restrict__ att,
                         const float* __restrict__ B,
                         float* __restrict__ out) {
    __shared__ float Wsl[8][128];
    __shared__ float Wsr[8][128];
    const int tid = threadIdx.x;
    for (int i = tid; i < 8 * 128 / 4; i += 256) {
        ((float4*)&Wsl[0][0])[i] = ((const float4*)Wl)[i];
        ((float4*)&Wsr[0][0])[i] = ((const float4*)Wr)[i];
    }
    __syncthreads();

    const int node = (blockIdx.x * blockDim.x + tid) >> 5;
    if (node >= NN) return;
    const int lane = tid & 31;

    // per-lane W slices in registers
    float4 wl[8];
#pragma unroll
    for (int k = 0; k < 8; k++) wl[k] = *(const float4*)&Wsl[k][lane * 4];

    const float4 attv = *(const float4*)(att + lane * 4);
    const float4 bl4  = *(const float4*)(Bl + lane * 4);

    // x[node] (broadcast 32B)
    const float4 xn0 = *(const float4*)(X + (size_t)node * 8);
    const float4 xn1 = *(const float4*)(X + (size_t)node * 8 + 4);
    float xn[8] = {xn0.x, xn0.y, xn0.z, xn0.w, xn1.x, xn1.y, xn1.z, xn1.w};

    // xr[node] = x@Wr + br  (lane's 4 channels)
    float4 xrv = *(const float4*)(Br + lane * 4);
#pragma unroll
    for (int k = 0; k < 8; k++) {
        const float4 wr = *(const float4*)&Wsr[k][lane * 4];
        xrv.x += xn[k] * wr.x; xrv.y += xn[k] * wr.y;
        xrv.z += xn[k] * wr.z; xrv.w += xn[k] * wr.w;
    }

    // s_self from xl[node]
    float s_self;
    {
        float4 xlv = bl4;
#pragma unroll
        for (int k = 0; k < 8; k++) {
            xlv.x += xn[k] * wl[k].x; xlv.y += xn[k] * wl[k].y;
            xlv.z += xn[k] * wl[k].z; xlv.w += xn[k] * wl[k].w;
        }
        float t, sc = 0.f;
        t = xlv.x + xrv.x; t = t > 0.f ? t : 0.2f * t; sc += t * attv.x;
        t = xlv.y + xrv.y; t = t > 0.f ? t : 0.2f * t; sc += t * attv.y;
        t = xlv.z + xrv.z; t = t > 0.f ? t : 0.2f * t; sc += t * attv.z;
        t = xlv.w + xrv.w; t = t > 0.f ? t : 0.2f * t; sc += t * attv.w;
#pragma unroll
        for (int off = 1; off <= 8; off <<= 1)
            sc += __shfl_xor_sync(0xffffffffu, sc, off);
        s_self = sc;
    }

    int p  = g_rowptr[node];
    const int pe = g_rowptr[node + 1];

    float  dd[2] = {0.f, 0.f};
    float4 A[2];
    A[0] = make_float4(0.f, 0.f, 0.f, 0.f);
    A[1] = make_float4(0.f, 0.f, 0.f, 0.f);

    for (; p + 1 < pe; p += 2) {
        const int s0 = g_csrc[p];
        const int s1 = g_csrc[p + 1];
        const float4 a0 = *(const float4*)(X + (size_t)s0 * 8);
        const float4 a1 = *(const float4*)(X + (size_t)s0 * 8 + 4);
        const float4 b0 = *(const float4*)(X + (size_t)s1 * 8);
        const float4 b1 = *(const float4*)(X + (size_t)s1 * 8 + 4);
        float xa[8] = {a0.x, a0.y, a0.z, a0.w, a1.x, a1.y, a1.z, a1.w};
        float xb[8] = {b0.x, b0.y, b0.z, b0.w, b1.x, b1.y, b1.z, b1.w};

        float4 xl0 = bl4, xl1 = bl4;
#pragma unroll
        for (int k = 0; k < 8; k++) {
            xl0.x += xa[k] * wl[k].x; xl0.y += xa[k] * wl[k].y;
            xl0.z += xa[k] * wl[k].z; xl0.w += xa[k] * wl[k].w;
            xl1.x += xb[k] * wl[k].x; xl1.y += xb[k] * wl[k].y;
            xl1.z += xb[k] * wl[k].z; xl1.w += xb[k] * wl[k].w;
        }

        float t, p0 = 0.f, p1 = 0.f;
        t = xl0.x + xrv.x; t = t > 0.f ? t : 0.2f * t; p0 += t * attv.x;
        t = xl1.x + xrv.x; t = t > 0.f ? t : 0.2f * t; p1 += t * attv.x;
        t = xl0.y + xrv.y; t = t > 0.f ? t : 0.2f * t; p0 += t * attv.y;
        t = xl1.y + xrv.y; t = t > 0.f ? t : 0.2f * t; p1 += t * attv.y;
        t = xl0.z + xrv.z; t = t > 0.f ? t : 0.2f * t; p0 += t * attv.z;
        t = xl1.z + xrv.z; t = t > 0.f ? t : 0.2f * t; p1 += t * attv.z;
        t = xl0.w + xrv.w; t = t > 0.f ? t : 0.2f * t; p0 += t * attv.w;
        t = xl1.w + xrv.w; t = t > 0.f ? t : 0.2f * t; p1 += t * attv.w;
#pragma unroll
        for (int off = 1; off <= 8; off <<= 1) {
            p0 += __shfl_xor_sync(0xffffffffu, p0, off);
            p1 += __shfl_xor_sync(0xffffffffu, p1, off);
        }
        const float w0 = __expf(p0 - s_self);
        const float w1 = __expf(p1 - s_self);
        dd[0] += w0; dd[1] += w1;
        A[0].x += w0 * xl0.x; A[0].y += w0 * xl0.y;
        A[0].z += w0 * xl0.z; A[0].w += w0 * xl0.w;
        A[1].x += w1 * xl1.x; A[1].y += w1 * xl1.y;
        A[1].z += w1 * xl1.z; A[1].w += w1 * xl1.w;
    }
    for (; p < pe; ++p) {
        const int s0 = g_csrc[p];
        const float4 a0 = *(const float4*)(X + (size_t)s0 * 8);
        const float4 a1 = *(const float4*)(X + (size_t)s0 * 8 + 4);
        float xa[8] = {a0.x, a0.y, a0.z, a0.w, a1.x, a1.y, a1.z, a1.w};
        float4 xl0 = bl4;
#pragma unroll
        for (int k = 0; k < 8; k++) {
            xl0.x += xa[k] * wl[k].x; xl0.y += xa[k] * wl[k].y;
            xl0.z += xa[k] * wl[k].z; xl0.w += xa[k] * wl[k].w;
        }
        float t, p0 = 0.f;
        t = xl0.x + xrv.x; t = t > 0.f ? t : 0.2f * t; p0 += t * attv.x;
        t = xl0.y + xrv.y; t = t > 0.f ? t : 0.2f * t; p0 += t * attv.y;
        t = xl0.z + xrv.z; t = t > 0.f ? t : 0.2f * t; p0 += t * attv.z;
        t = xl0.w + xrv.w; t = t > 0.f ? t : 0.2f * t; p0 += t * attv.w;
#pragma unroll
        for (int off = 1; off <= 8; off <<= 1)
            p0 += __shfl_xor_sync(0xffffffffu, p0, off);
        const float w0 = __expf(p0 - s_self);
        dd[0] += w0;
        A[0].x += w0 * xl0.x; A[0].y += w0 * xl0.y;
        A[0].z += w0 * xl0.z; A[0].w += w0 * xl0.w;
    }

    const float inv = 1.f / (dd[0] + dd[1]);
    const float4 bv = *(const float4*)(B + lane * 4);
    float4 o;
    o.x = (A[0].x + A[1].x) * inv + bv.x; o.x = o.x > 0.f ? o.x : expm1f(o.x);
    o.y = (A[0].y + A[1].y) * inv + bv.y; o.y = o.y > 0.f ? o.y : expm1f(o.y);
    o.z = (A[0].z + A[1].z) * inv + bv.z; o.z = o.z > 0.f ? o.z : expm1f(o.z);
    o.w = (A[0].w + A[1].w) * inv + bv.w; o.w = o.w > 0.f ? o.w : expm1f(o.w);
    *(float4*)(out + (size_t)node * 128 + lane * 4) = o;
}

// ---------------- dual linear: Yl = X@Wl+Bl, Yr = X@Wr+Br -------------------
template<int IN, int OUT>
__global__ __launch_bounds__(256)
void linear_dual_kernel(const float* __restrict__ X,
                        const float* __restrict__ Wl, const float* __restrict__ Bl,
                        const float* __restrict__ Wr, const float* __restrict__ Br,
                        float* __restrict__ Yl, float* __restrict__ Yr) {
    constexpr int TO  = OUT / 8;
    constexpr int NGR = 256 / TO;
    constexpr int NPB = NGR * 4;
    constexpr int KT  = (IN < 32) ? IN : 32;

    __shared__ float Xs[KT][NPB + 4];
    __shared__ float Wsl[KT][OUT];
    __shared__ float Wsr[KT][OUT];

    const int tid = threadIdx.x;
    const int og  = tid % TO;
    const int ng  = tid / TO;
    const int nb  = blockIdx.x * NPB;

    float accl[4][8], accr[4][8];
#pragma unroll
    for (int i = 0; i < 4; i++)
#pragma unroll
        for (int j = 0; j < 8; j++) { accl[i][j] = 0.f; accr[i][j] = 0.f; }

    for (int kt = 0; kt < IN; kt += KT) {
        __syncthreads();
        for (int idx = tid; idx < KT * OUT / 4; idx += 256) {
            const int k = idx / (OUT / 4), o4 = idx % (OUT / 4);
            ((float4*)Wsl[k])[o4] = ((const float4*)(Wl + (size_t)(kt + k) * OUT))[o4];
            ((float4*)Wsr[k])[o4] = ((const float4*)(Wr + (size_t)(kt + k) * OUT))[o4];
        }
        for (int idx = tid; idx < NPB * (KT / 4); idx += 256) {
            const int ni = idx / (KT / 4), f4 = idx % (KT / 4);
            const int gn = nb + ni;
            float4 xv = make_float4(0.f, 0.f, 0.f, 0.f);
            if (gn < NN)
                xv = ((const float4*)(X + (size_t)gn * IN + kt))[f4];
            Xs[f4 * 4 + 0][ni] = xv.x;
            Xs[f4 * 4 + 1][ni] = xv.y;
            Xs[f4 * 4 + 2][ni] = xv.z;
            Xs[f4 * 4 + 3][ni] = xv.w;
        }
        __syncthreads();
#pragma unroll
        for (int k = 0; k < KT; k++) {
            float xv[4];
#pragma unroll
            for (int i = 0; i < 4; i++) xv[i] = Xs[k][ng * 4 + i];
            const float4 wl0 = ((const float4*)&Wsl[k][og * 8])[0];
            const float4 wl1 = ((const float4*)&Wsl[k][og * 8])[1];
            const float4 wr0 = ((const float4*)&Wsr[k][og * 8])[0];
            const float4 wr1 = ((const float4*)&Wsr[k][og * 8])[1];
#pragma unroll
            for (int i = 0; i < 4; i++) {
                accl[i][0] += xv[i] * wl0.x; accl[i][1] += xv[i] * wl0.y;
                accl[i][2] += xv[i] * wl0.z; accl[i][3] += xv[i] * wl0.w;
                accl[i][4] += xv[i] * wl1.x; accl[i][5] += xv[i] * wl1.y;
                accl[i][6] += xv[i] * wl1.z; accl[i][7] += xv[i] * wl1.w;
                accr[i][0] += xv[i] * wr0.x; accr[i][1] += xv[i] * wr0.y;
                accr[i][2] += xv[i] * wr0.z; accr[i][3] += xv[i] * wr0.w;
                accr[i][4] += xv[i] * wr1.x; accr[i][5] += xv[i] * wr1.y;
                accr[i][6] += xv[i] * wr1.z; accr[i][7] += xv[i] * wr1.w;
            }
        }
    }

    const float4 bl0 = ((const float4*)(Bl + og * 8))[0];
    const float4 bl1 = ((const float4*)(Bl + og * 8))[1];
    const float4 br0 = ((const float4*)(Br + og * 8))[0];
    const float4 br1 = ((const float4*)(Br + og * 8))[1];
#pragma unroll
    for (int i = 0; i < 4; i++) {
        const int node = nb + ng * 4 + i;
        if (node >= NN) continue;
        float4 o;
        o = make_float4(accl[i][0]+bl0.x, accl[i][1]+bl0.y, accl[i][2]+bl0.z, accl[i][3]+bl0.w);
        ((float4*)(Yl + (size_t)node * OUT + og * 8))[0] = o;
        o = make_float4(accl[i][4]+bl1.x, accl[i][5]+bl1.y, accl[i][6]+bl1.z, accl[i][7]+bl1.w);
        ((float4*)(Yl + (size_t)node * OUT + og * 8))[1] = o;
        o = make_float4(accr[i][0]+br0.x, accr[i][1]+br0.y, accr[i][2]+br0.z, accr[i][3]+br0.w);
        ((float4*)(Yr + (size_t)node * OUT + og * 8))[0] = o;
        o = make_float4(accr[i][4]+br1.x, accr[i][5]+br1.y, accr[i][6]+br1.z, accr[i][7]+br1.w);
        ((float4*)(Yr + (size_t)node * OUT + og * 8))[1] = o;
    }
}

// ---------------- fused GATv2 edge pass (CT=128, H=2), warp/dst, ILP4 -------
__global__ void gat_fused128_kernel(const float* __restrict__ att,
                                    const float* __restrict__ B,
                                    float* __restrict__ out) {
    const int node = (blockIdx.x * blockDim.x + threadIdx.x) >> 5;
    if (node >= NN) return;
    const int lane = threadIdx.x & 31;

    const float4 xrv  = *(const float4*)(g_xr + (size_t)node * 128 + lane * 4);
    const float4 attv = *(const float4*)(att + lane * 4);

    float s_self;
    {
        const float4 xlv = *(const float4*)(g_xl + (size_t)node * 128 + lane * 4);
        float t, sc = 0.f;
        t = xlv.x + xrv.x; t = t > 0.f ? t : 0.2f * t; sc += t * attv.x;
        t = xlv.y + xrv.y; t = t > 0.f ? t : 0.2f * t; sc += t * attv.y;
        t = xlv.z + xrv.z; t = t > 0.f ? t : 0.2f * t; sc += t * attv.z;
        t = xlv.w + xrv.w; t = t > 0.f ? t : 0.2f * t; sc += t * attv.w;
#pragma unroll
        for (int off = 1; off <= 8; off <<= 1)
            sc += __shfl_xor_sync(0xffffffffu, sc, off);
        s_self = sc;
    }

    int p  = g_rowptr[node];
    const int pe = g_rowptr[node + 1];

    float  dd[4] = {0.f, 0.f, 0.f, 0.f};
    float4 A[4];
#pragma unroll
    for (int j = 0; j < 4; j++) A[j] = make_float4(0.f, 0.f, 0.f, 0.f);

    for (; p + 3 < pe; p += 4) {
        int s[4];
#pragma unroll
        for (int j = 0; j < 4; j++) s[j] = g_csrc[p + j];
        float4 a[4];
#pragma unroll
        for (int j = 0; j < 4; j++)
            a[j] = *(const float4*)(g_xl + (size_t)s[j] * 128 + lane * 4);

        float pp[4];
#pragma unroll
        for (int j = 0; j < 4; j++) {
            float t, sc = 0.f;
            t = a[j].x + xrv.x; t = t > 0.f ? t : 0.2f * t; sc += t * attv.x;
            t = a[j].y + xrv.y; t = t > 0.f ? t : 0.2f * t; sc += t * attv.y;
            t = a[j].z + xrv.z; t = t > 0.f ? t : 0.2f * t; sc += t * attv.z;
            t = a[j].w + xrv.w; t = t > 0.f ? t : 0.2f * t; sc += t * attv.w;
            pp[j] = sc;
        }
#pragma unroll
        for (int off = 1; off <= 8; off <<= 1)
#pragma unroll
            for (int j = 0; j < 4; j++)
                pp[j] += __shfl_xor_sync(0xffffffffu, pp[j], off);
#pragma unroll
        for (int j = 0; j < 4; j++) {
            const float w = __expf(pp[j] - s_self);
            dd[j] += w;
            A[j].x += w * a[j].x;
            A[j].y += w * a[j].y;
            A[j].z += w * a[j].z;
            A[j].w += w * a[j].w;
        }
    }
    for (; p < pe; ++p) {
        const int s0 = g_csrc[p];
        const float4 a0 = *(const float4*)(g_xl + (size_t)s0 * 128 + lane * 4);
        float t, p0 = 0.f;
        t = a0.x + xrv.x; t = t > 0.f ? t : 0.2f * t; p0 += t * attv.x;
        t = a0.y + xrv.y; t = t > 0.f ? t : 0.2f * t; p0 += t * attv.y;
        t = a0.z + xrv.z; t = t > 0.f ? t : 0.2f * t; p0 += t * attv.z;
        t = a0.w + xrv.w; t = t > 0.f ? t : 0.2f * t; p0 += t * attv.w;
#pragma unroll
        for (int off = 1; off <= 8; off <<= 1)
            p0 += __shfl_xor_sync(0xffffffffu, p0, off);
        const float w = __expf(p0 - s_self);
        dd[0] += w;
        A[0].x += w * a0.x;
        A[0].y += w * a0.y;
        A[0].z += w * a0.z;
        A[0].w += w * a0.w;
    }

    const float d = dd[0] + dd[1] + dd[2] + dd[3];
    float4 acc;
    acc.x = A[0].x + A[1].x + A[2].x + A[3].x;
    acc.y = A[0].y + A[1].y + A[2].y + A[3].y;
    acc.z = A[0].z + A[1].z + A[2].z + A[3].z;
    acc.w = A[0].w + A[1].w + A[2].w + A[3].w;

    const float inv = 1.f / d;
    const float4 bv = *(const float4*)(B + lane * 4);
    float4 o;
    o.x = acc.x * inv + bv.x; o.x = o.x > 0.f ? o.x : expm1f(o.x);
    o.y = acc.y * inv + bv.y; o.y = o.y > 0.f ? o.y : expm1f(o.y);
    o.z = acc.z * inv + bv.z; o.z = o.z > 0.f ? o.z : expm1f(o.z);
    o.w = acc.w * inv + bv.w; o.w = o.w > 0.f ? o.w : expm1f(o.w);
    *(float4*)(out + (size_t)node * 128 + lane * 4) = o;
}

// ---------------- fused GATv2 edge pass (CT=32, H=1), warp/dst, ILP4 --------
__global__ void gat_fused32_kernel(const float* __restrict__ att,
                                   const float* __restrict__ B,
                                   float* __restrict__ out) {
    const int node = (blockIdx.x * blockDim.x + threadIdx.x) >> 5;
    if (node >= NN) return;
    const int lane = threadIdx.x & 31;

    const float xrv  = g_xr[(size_t)node * 32 + lane];
    const float attv = att[lane];

    float s_self;
    {
        const float xlv = g_xl[(size_t)node * 32 + lane];
        float t = xlv + xrv; t = t > 0.f ? t : 0.2f * t;
        float sc = t * attv;
#pragma unroll
        for (int off = 1; off <= 16; off <<= 1)
            sc += __shfl_xor_sync(0xffffffffu, sc, off);
        s_self = sc;
    }

    int p  = g_rowptr[node];
    const int pe = g_rowptr[node + 1];

    float dd[4] = {0.f, 0.f, 0.f, 0.f};
    float A[4] = {0.f, 0.f, 0.f, 0.f};

    for (; p + 3 < pe; p += 4) {
        float a[4], pp[4];
#pragma unroll
        for (int j = 0; j < 4; j++) {
            const int s = g_csrc[p + j];
            a[j] = g_xl[(size_t)s * 32 + lane];
            float t = a[j] + xrv; t = t > 0.f ? t : 0.2f * t;
            pp[j] = t * attv;
        }
#pragma unroll
        for (int off = 1; off <= 16; off <<= 1)
#pragma unroll
            for (int j = 0; j < 4; j++)
                pp[j] += __shfl_xor_sync(0xffffffffu, pp[j], off);
#pragma unroll
        for (int j = 0; j < 4; j++) {
            const float w = __expf(pp[j] - s_self);
            dd[j] += w; A[j] += w * a[j];
        }
    }
    for (; p < pe; ++p) {
        const int s = g_csrc[p];
        const float a0 = g_xl[(size_t)s * 32 + lane];
        float t = a0 + xrv; t = t > 0.f ? t : 0.2f * t;
        float p0 = t * attv;
#pragma unroll
        for (int off = 1; off <= 16; off <<= 1)
            p0 += __shfl_xor_sync(0xffffffffu, p0, off);
        const float w = __expf(p0 - s_self);
        dd[0] += w; A[0] += w * a0;
    }

    const float d = dd[0] + dd[1] + dd[2] + dd[3];
    const float acc = A[0] + A[1] + A[2] + A[3];

    float o = acc / d + B[lane];
    o = o > 0.f ? o : expm1f(o);
    out[(size_t)node * 32 + lane] = o;
}

// ---------------- pooling ----------------------------------------------------
__global__ void pool_init_kernel() {
    int i = blockIdx.x * blockDim.x + threadIdx.x;
    if (i < NG * 32) { g_psum[i] = 0.f; g_pmax[i] = -INFINITY; }
    if (i < NG) g_cntf[i] = 0.f;
}

__global__ __launch_bounds__(256)
void pool_accum_kernel(const float* __restrict__ h,
                       const int* __restrict__ batch) {
    __shared__ float ssum[NG * 32];
    __shared__ float smax[NG * 32];
    __shared__ int   scnt[NG];
    const int tid = threadIdx.x;
    for (int i = tid; i < NG * 32; i += 256) { ssum[i] = 0.f; smax[i] = -INFINITY; }
    if (tid < NG) scnt[tid] = 0;
    __syncthreads();

    const int warp = tid >> 5, lane = tid & 31;
    const int nbase = blockIdx.x * 256 + warp * 32;
#pragma unroll 4
    for (int i = 0; i < 32; i++) {
        const int node = nbase + i;
        if (node >= NN) break;
        const int g = batch[node];
        const float v = h[(size_t)node * 32 + lane];
        atomicAdd(&ssum[g * 32 + lane], v);
        atomicMaxF(&smax[g * 32 + lane], v);
        if (lane == 0) atomicAdd(&scnt[g], 1);
    }
    __syncthreads();

    for (int i = tid; i < NG * 32; i += 256) {
        if (ssum[i] != 0.f) atomicAdd(&g_psum[i], ssum[i]);
        if (smax[i] != -INFINITY) atomicMaxF(&g_pmax[i], smax[i]);
    }
    if (tid < NG && scnt[tid] > 0) atomicAdd(&g_cntf[tid], (float)scnt[tid]);
}

__global__ void pool_final_kernel(float* __restrict__ out) {
    const int i = blockIdx.x * blockDim.x + threadIdx.x;
    if (i >= NG * 64) return;
    const int g = i / 64, c = i % 64;
    out[i] = (c < 32) ? g_psum[g * 32 + c] / g_cntf[g]
                      : g_pmax[g * 32 + (c - 32)];
}

// ---------------- launch ------------------------------------------------------
static inline int gridFor(long long n) { return (int)((n + TB - 1) / TB); }

extern "C" void kernel_launch(void* const* d_in, const int* in_sizes, int n_in,
                              void* d_out, int out_size) {
    const float* x     = (const float*)d_in[0];
    const int*   ei    = (const int*)d_in[1];
    const int*   batch = (const int*)d_in[2];
    const float *Wl1=(const float*)d_in[3],  *bl1=(const float*)d_in[4];
    const float *Wr1=(const float*)d_in[5],  *br1=(const float*)d_in[6];
    const float *att1=(const float*)d_in[7], *b1=(const float*)d_in[8];
    const float *Wl2=(const float*)d_in[9],  *bl2=(const float*)d_in[10];
    const float *Wr2=(const float*)d_in[11], *br2=(const float*)d_in[12];
    const float *att2=(const float*)d_in[13],*b2=(const float*)d_in[14];
    const float *Wl3=(const float*)d_in[15], *bl3=(const float*)d_in[16];
    const float *Wr3=(const float*)d_in[17], *br3=(const float*)d_in[18];
    const float *att3=(const float*)d_in[19],*b3=(const float*)d_in[20];

    float *p_xl, *p_xr, *p_h;
    cudaGetSymbolAddress((void**)&p_xl, g_xl);
    cudaGetSymbolAddress((void**)&p_xr, g_xr);
    cudaGetSymbolAddress((void**)&p_h,  g_h);

    const int gNodeWarp = gridFor((long long)NN * 32);
    const int gLin128   = (NN + 63) / 64;
    const int gLin32    = (NN + 255) / 256;
    const int gPool     = (NN + 255) / 256;

    // ---- CSR (dst-indexed) build (g_deg starts 0; fill re-zeroes it)
    deg_count_kernel<<<gridFor(NE), TB>>>(ei);                      // 1
    scan_kernel<<<1, 1024>>>();                                     // 2
    fill_kernel<<<gridFor(ET), TB>>>(ei);                           // 3

    // ---- layer 1: 8 -> 128 (H=2, C=64), fully fused (no linear needed)
    gat_fused_l1_kernel<<<gNodeWarp, TB>>>(x, Wl1, bl1, Wr1, br1,
                                           att1, b1, p_h);          // 4 (profiled)

    // ---- layer 2: 128 -> 128 (H=2, C=64)
    linear_dual_kernel<128, 128><<<gLin128, 256>>>(p_h, Wl2, bl2, Wr2, br2, p_xl, p_xr);
    gat_fused128_kernel<<<gNodeWarp, TB>>>(att2, b2, p_h);

    // ---- layer 3: 128 -> 32 (H=1, C=32)
    linear_dual_kernel<128, 32><<<gLin32, 256>>>(p_h, Wl3, bl3, Wr3, br3, p_xl, p_xr);
    gat_fused32_kernel<<<gNodeWarp, TB>>>(att3, b3, p_h);

    // ---- pooling
    pool_init_kernel<<<gridFor(NG * 32), TB>>>();
    pool_accum_kernel<<<gPool, 256>>>(p_h, batch);
    pool_final_kernel<<<gridFor(NG * 64), TB>>>((float*)d_out);
}

// round 11
// speedup vs baseline: 1.0233x; 1.0233x over previous
#include <cuda_runtime.h>
#include <math.h>

// GATv2 x3 + pooling: CSR + offset-softmax fused edge pass (ILP8 gathers),
// dual (Wl+Wr) register-tiled linears, SMEM pooling.
namespace {
constexpr int NN = 50000;
constexpr int NE = 800000;
constexpr int ET = NE + NN;
constexpr int NG = 16;
constexpr int TB = 256;
}

// ---------------- scratch ---------------------------------------------------
__device__ __align__(16) float g_xl[(size_t)NN * 128];
__device__ __align__(16) float g_xr[(size_t)NN * 128];
__device__ __align__(16) float g_h[(size_t)NN * 128];
__device__ int g_deg[NN];            // zero at load; re-zeroed in fill
__device__ int g_rowptr[NN + 1];
__device__ int g_cur[NN];
__device__ int g_csrc[ET];
__device__ float g_psum[NG * 32];
__device__ float g_pmax[NG * 32];
__device__ float g_cntf[NG];

__device__ __forceinline__ void atomicMaxF(float* a, float v) {
    if (v >= 0.f) atomicMax((int*)a, __float_as_int(v));
    else          atomicMin((unsigned int*)a, __float_as_uint(v));
}

// ---------------- CSR build -------------------------------------------------
__global__ void deg_count_kernel(const int* __restrict__ ei) {
    int e = blockIdx.x * blockDim.x + threadIdx.x;
    if (e < NE) atomicAdd(&g_deg[ei[NE + e]], 1);
}
__global__ void scan_kernel() {
    __shared__ int part[1024];
    const int tid = threadIdx.x;
    const int chunk = (NN + 1023) / 1024;
    const int beg = tid * chunk;
    const int end = min(beg + chunk, NN);
    int s = 0;
    for (int i = beg; i < end; i++) s += g_deg[i] + 1;   // +1 self loop
    part[tid] = s;
    __syncthreads();
    if (tid == 0) {
        int run = 0;
        for (int i = 0; i < 1024; i++) { int t = part[i]; part[i] = run; run += t; }
    }
    __syncthreads();
    int run = part[tid];
    for (int i = beg; i < end; i++) {
        g_rowptr[i] = run;
        g_cur[i] = run;
        run += g_deg[i] + 1;
    }
    if (tid == 0) g_rowptr[NN] = ET;
}
__global__ void fill_kernel(const int* __restrict__ ei) {
    int e = blockIdx.x * blockDim.x + threadIdx.x;
    if (e < NN) g_deg[e] = 0;        // re-zero for next replay
    if (e >= ET) return;
    int src, dst;
    if (e < NE) { src = ei[e]; dst = ei[NE + e]; }
    else        { src = e - NE; dst = src; }
    int pos = atomicAdd(&g_cur[dst], 1);
    g_csrc[pos] = src;
}

// ---------------- dual linear: Yl = X@Wl+Bl, Yr = X@Wr+Br -------------------
template<int IN, int OUT>
__global__ __launch_bounds__(256)
void linear_dual_kernel(const float* __restrict__ X,
                        const float* __restrict__ Wl, const float* __restrict__ Bl,
                        const float* __restrict__ Wr, const float* __restrict__ Br,
                        float* __restrict__ Yl, float* __restrict__ Yr) {
    constexpr int TO  = OUT / 8;
    constexpr int NGR = 256 / TO;
    constexpr int NPB = NGR * 4;
    constexpr int KT  = (IN < 32) ? IN : 32;

    __shared__ float Xs[KT][NPB + 4];
    __shared__ float Wsl[KT][OUT];
    __shared__ float Wsr[KT][OUT];

    const int tid = threadIdx.x;
    const int og  = tid % TO;
    const int ng  = tid / TO;
    const int nb  = blockIdx.x * NPB;

    float accl[4][8], accr[4][8];
#pragma unroll
    for (int i = 0; i < 4; i++)
#pragma unroll
        for (int j = 0; j < 8; j++) { accl[i][j] = 0.f; accr[i][j] = 0.f; }

    for (int kt = 0; kt < IN; kt += KT) {
        __syncthreads();
        for (int idx = tid; idx < KT * OUT / 4; idx += 256) {
            const int k = idx / (OUT / 4), o4 = idx % (OUT / 4);
            ((float4*)Wsl[k])[o4] = ((const float4*)(Wl + (size_t)(kt + k) * OUT))[o4];
            ((float4*)Wsr[k])[o4] = ((const float4*)(Wr + (size_t)(kt + k) * OUT))[o4];
        }
        for (int idx = tid; idx < NPB * (KT / 4); idx += 256) {
            const int ni = idx / (KT / 4), f4 = idx % (KT / 4);
            const int gn = nb + ni;
            float4 xv = make_float4(0.f, 0.f, 0.f, 0.f);
            if (gn < NN)
                xv = ((const float4*)(X + (size_t)gn * IN + kt))[f4];
            Xs[f4 * 4 + 0][ni] = xv.x;
            Xs[f4 * 4 + 1][ni] = xv.y;
            Xs[f4 * 4 + 2][ni] = xv.z;
            Xs[f4 * 4 + 3][ni] = xv.w;
        }
        __syncthreads();
#pragma unroll
        for (int k = 0; k < KT; k++) {
            float xv[4];
#pragma unroll
            for (int i = 0; i < 4; i++) xv[i] = Xs[k][ng * 4 + i];
            const float4 wl0 = ((const float4*)&Wsl[k][og * 8])[0];
            const float4 wl1 = ((const float4*)&Wsl[k][og * 8])[1];
            const float4 wr0 = ((const float4*)&Wsr[k][og * 8])[0];
            const float4 wr1 = ((const float4*)&Wsr[k][og * 8])[1];
#pragma unroll
            for (int i = 0; i < 4; i++) {
                accl[i][0] += xv[i] * wl0.x; accl[i][1] += xv[i] * wl0.y;
                accl[i][2] += xv[i] * wl0.z; accl[i][3] += xv[i] * wl0.w;
                accl[i][4] += xv[i] * wl1.x; accl[i][5] += xv[i] * wl1.y;
                accl[i][6] += xv[i] * wl1.z; accl[i][7] += xv[i] * wl1.w;
                accr[i][0] += xv[i] * wr0.x; accr[i][1] += xv[i] * wr0.y;
                accr[i][2] += xv[i] * wr0.z; accr[i][3] += xv[i] * wr0.w;
                accr[i][4] += xv[i] * wr1.x; accr[i][5] += xv[i] * wr1.y;
                accr[i][6] += xv[i] * wr1.z; accr[i][7] += xv[i] * wr1.w;
            }
        }
    }

    const float4 bl0 = ((const float4*)(Bl + og * 8))[0];
    const float4 bl1 = ((const float4*)(Bl + og * 8))[1];
    const float4 br0 = ((const float4*)(Br + og * 8))[0];
    const float4 br1 = ((const float4*)(Br + og * 8))[1];
#pragma unroll
    for (int i = 0; i < 4; i++) {
        const int node = nb + ng * 4 + i;
        if (node >= NN) continue;
        float4 o;
        o = make_float4(accl[i][0]+bl0.x, accl[i][1]+bl0.y, accl[i][2]+bl0.z, accl[i][3]+bl0.w);
        ((float4*)(Yl + (size_t)node * OUT + og * 8))[0] = o;
        o = make_float4(accl[i][4]+bl1.x, accl[i][5]+bl1.y, accl[i][6]+bl1.z, accl[i][7]+bl1.w);
        ((float4*)(Yl + (size_t)node * OUT + og * 8))[1] = o;
        o = make_float4(accr[i][0]+br0.x, accr[i][1]+br0.y, accr[i][2]+br0.z, accr[i][3]+br0.w);
        ((float4*)(Yr + (size_t)node * OUT + og * 8))[0] = o;
        o = make_float4(accr[i][4]+br1.x, accr[i][5]+br1.y, accr[i][6]+br1.z, accr[i][7]+br1.w);
        ((float4*)(Yr + (size_t)node * OUT + og * 8))[1] = o;
    }
}

// ---------------- fused GATv2 edge pass (CT=128, H=2), warp/dst, ILP8 -------
// offset softmax: w = exp(s - s_self); 8 gathers in flight, 2 accumulators.
__global__ __launch_bounds__(256)
void gat_fused128_kernel(const float* __restrict__ att,
                         const float* __restrict__ B,
                         float* __restrict__ out) {
    const int node = (blockIdx.x * blockDim.x + threadIdx.x) >> 5;
    if (node >= NN) return;
    const int lane = threadIdx.x & 31;

    const float4 xrv  = *(const float4*)(g_xr + (size_t)node * 128 + lane * 4);
    const float4 attv = *(const float4*)(att + lane * 4);

    float s_self;
    {
        const float4 xlv = *(const float4*)(g_xl + (size_t)node * 128 + lane * 4);
        float t, sc = 0.f;
        t = xlv.x + xrv.x; t = t > 0.f ? t : 0.2f * t; sc += t * attv.x;
        t = xlv.y + xrv.y; t = t > 0.f ? t : 0.2f * t; sc += t * attv.y;
        t = xlv.z + xrv.z; t = t > 0.f ? t : 0.2f * t; sc += t * attv.z;
        t = xlv.w + xrv.w; t = t > 0.f ? t : 0.2f * t; sc += t * attv.w;
#pragma unroll
        for (int off = 1; off <= 8; off <<= 1)
            sc += __shfl_xor_sync(0xffffffffu, sc, off);
        s_self = sc;
    }

    int p  = g_rowptr[node];
    const int pe = g_rowptr[node + 1];

    float  dd0 = 0.f, dd1 = 0.f;
    float4 A0 = make_float4(0.f, 0.f, 0.f, 0.f);
    float4 A1 = make_float4(0.f, 0.f, 0.f, 0.f);

    for (; p + 7 < pe; p += 8) {
        float4 a[8];
#pragma unroll
        for (int j = 0; j < 8; j++) {
            const int s = g_csrc[p + j];
            a[j] = *(const float4*)(g_xl + (size_t)s * 128 + lane * 4);
        }
        float pp[8];
#pragma unroll
        for (int j = 0; j < 8; j++) {
            float t, sc = 0.f;
            t = a[j].x + xrv.x; t = t > 0.f ? t : 0.2f * t; sc += t * attv.x;
            t = a[j].y + xrv.y; t = t > 0.f ? t : 0.2f * t; sc += t * attv.y;
            t = a[j].z + xrv.z; t = t > 0.f ? t : 0.2f * t; sc += t * attv.z;
            t = a[j].w + xrv.w; t = t > 0.f ? t : 0.2f * t; sc += t * attv.w;
            pp[j] = sc;
        }
#pragma unroll
        for (int off = 1; off <= 8; off <<= 1)
#pragma unroll
            for (int j = 0; j < 8; j++)
                pp[j] += __shfl_xor_sync(0xffffffffu, pp[j], off);
#pragma unroll
        for (int j = 0; j < 8; j += 2) {
            const float w0 = __expf(pp[j]     - s_self);
            const float w1 = __expf(pp[j + 1] - s_self);
            dd0 += w0; dd1 += w1;
            A0.x += w0 * a[j].x;     A0.y += w0 * a[j].y;
            A0.z += w0 * a[j].z;     A0.w += w0 * a[j].w;
            A1.x += w1 * a[j + 1].x; A1.y += w1 * a[j + 1].y;
            A1.z += w1 * a[j + 1].z; A1.w += w1 * a[j + 1].w;
        }
    }
    for (; p < pe; ++p) {
        const int s0 = g_csrc[p];
        const float4 a0 = *(const float4*)(g_xl + (size_t)s0 * 128 + lane * 4);
        float t, p0 = 0.f;
        t = a0.x + xrv.x; t = t > 0.f ? t : 0.2f * t; p0 += t * attv.x;
        t = a0.y + xrv.y; t = t > 0.f ? t : 0.2f * t; p0 += t * attv.y;
        t = a0.z + xrv.z; t = t > 0.f ? t : 0.2f * t; p0 += t * attv.z;
        t = a0.w + xrv.w; t = t > 0.f ? t : 0.2f * t; p0 += t * attv.w;
#pragma unroll
        for (int off = 1; off <= 8; off <<= 1)
            p0 += __shfl_xor_sync(0xffffffffu, p0, off);
        const float w = __expf(p0 - s_self);
        dd0 += w;
        A0.x += w * a0.x; A0.y += w * a0.y;
        A0.z += w * a0.z; A0.w += w * a0.w;
    }

    const float inv = 1.f / (dd0 + dd1);
    const float4 bv = *(const float4*)(B + lane * 4);
    float4 o;
    o.x = (A0.x + A1.x) * inv + bv.x; o.x = o.x > 0.f ? o.x : expm1f(o.x);
    o.y = (A0.y + A1.y) * inv + bv.y; o.y = o.y > 0.f ? o.y : expm1f(o.y);
    o.z = (A0.z + A1.z) * inv + bv.z; o.z = o.z > 0.f ? o.z : expm1f(o.z);
    o.w = (A0.w + A1.w) * inv + bv.w; o.w = o.w > 0.f ? o.w : expm1f(o.w);
    *(float4*)(out + (size_t)node * 128 + lane * 4) = o;
}

// ---------------- fused GATv2 edge pass (CT=32, H=1), warp/dst, ILP4 --------
__global__ void gat_fused32_kernel(const float* __restrict__ att,
                                   const float* __restrict__ B,
                                   float* __restrict__ out) {
    const int node = (blockIdx.x * blockDim.x + threadIdx.x) >> 5;
    if (node >= NN) return;
    const int lane = threadIdx.x & 31;

    const float xrv  = g_xr[(size_t)node * 32 + lane];
    const float attv = att[lane];

    float s_self;
    {
        const float xlv = g_xl[(size_t)node * 32 + lane];
        float t = xlv + xrv; t = t > 0.f ? t : 0.2f * t;
        float sc = t * attv;
#pragma unroll
        for (int off = 1; off <= 16; off <<= 1)
            sc += __shfl_xor_sync(0xffffffffu, sc, off);
        s_self = sc;
    }

    int p  = g_rowptr[node];
    const int pe = g_rowptr[node + 1];

    float dd[4] = {0.f, 0.f, 0.f, 0.f};
    float A[4] = {0.f, 0.f, 0.f, 0.f};

    for (; p + 3 < pe; p += 4) {
        float a[4], pp[4];
#pragma unroll
        for (int j = 0; j < 4; j++) {
            const int s = g_csrc[p + j];
            a[j] = g_xl[(size_t)s * 32 + lane];
            float t = a[j] + xrv; t = t > 0.f ? t : 0.2f * t;
            pp[j] = t * attv;
        }
#pragma unroll
        for (int off = 1; off <= 16; off <<= 1)
#pragma unroll
            for (int j = 0; j < 4; j++)
                pp[j] += __shfl_xor_sync(0xffffffffu, pp[j], off);
#pragma unroll
        for (int j = 0; j < 4; j++) {
            const float w = __expf(pp[j] - s_self);
            dd[j] += w; A[j] += w * a[j];
        }
    }
    for (; p < pe; ++p) {
        const int s = g_csrc[p];
        const float a0 = g_xl[(size_t)s * 32 + lane];
        float t = a0 + xrv; t = t > 0.f ? t : 0.2f * t;
        float p0 = t * attv;
#pragma unroll
        for (int off = 1; off <= 16; off <<= 1)
            p0 += __shfl_xor_sync(0xffffffffu, p0, off);
        const float w = __expf(p0 - s_self);
        dd[0] += w; A[0] += w * a0;
    }

    const float d = dd[0] + dd[1] + dd[2] + dd[3];
    const float acc = A[0] + A[1] + A[2] + A[3];

    float o = acc / d + B[lane];
    o = o > 0.f ? o : expm1f(o);
    out[(size_t)node * 32 + lane] = o;
}

// ---------------- pooling ----------------------------------------------------
__global__ void pool_init_kernel() {
    int i = blockIdx.x * blockDim.x + threadIdx.x;
    if (i < NG * 32) { g_psum[i] = 0.f; g_pmax[i] = -INFINITY; }
    if (i < NG) g_cntf[i] = 0.f;
}

__global__ __launch_bounds__(256)
void pool_accum_kernel(const float* __restrict__ h,
                       const int* __restrict__ batch) {
    __shared__ float ssum[NG * 32];
    __shared__ float smax[NG * 32];
    __shared__ int   scnt[NG];
    const int tid = threadIdx.x;
    for (int i = tid; i < NG * 32; i += 256) { ssum[i] = 0.f; smax[i] = -INFINITY; }
    if (tid < NG) scnt[tid] = 0;
    __syncthreads();

    const int warp = tid >> 5, lane = tid & 31;
    const int nbase = blockIdx.x * 256 + warp * 32;
#pragma unroll 4
    for (int i = 0; i < 32; i++) {
        const int node = nbase + i;
        if (node >= NN) break;
        const int g = batch[node];
        const float v = h[(size_t)node * 32 + lane];
        atomicAdd(&ssum[g * 32 + lane], v);
        atomicMaxF(&smax[g * 32 + lane], v);
        if (lane == 0) atomicAdd(&scnt[g], 1);
    }
    __syncthreads();

    for (int i = tid; i < NG * 32; i += 256) {
        if (ssum[i] != 0.f) atomicAdd(&g_psum[i], ssum[i]);
        if (smax[i] != -INFINITY) atomicMaxF(&g_pmax[i], smax[i]);
    }
    if (tid < NG && scnt[tid] > 0) atomicAdd(&g_cntf[tid], (float)scnt[tid]);
}

__global__ void pool_final_kernel(float* __restrict__ out) {
    const int i = blockIdx.x * blockDim.x + threadIdx.x;
    if (i >= NG * 64) return;
    const int g = i / 64, c = i % 64;
    out[i] = (c < 32) ? g_psum[g * 32 + c] / g_cntf[g]
                      : g_pmax[g * 32 + (c - 32)];
}

// ---------------- launch ------------------------------------------------------
static inline int gridFor(long long n) { return (int)((n + TB - 1) / TB); }

extern "C" void kernel_launch(void* const* d_in, const int* in_sizes, int n_in,
                              void* d_out, int out_size) {
    const float* x     = (const float*)d_in[0];
    const int*   ei    = (const int*)d_in[1];
    const int*   batch = (const int*)d_in[2];
    const float *Wl1=(const float*)d_in[3],  *bl1=(const float*)d_in[4];
    const float *Wr1=(const float*)d_in[5],  *br1=(const float*)d_in[6];
    const float *att1=(const float*)d_in[7], *b1=(const float*)d_in[8];
    const float *Wl2=(const float*)d_in[9],  *bl2=(const float*)d_in[10];
    const float *Wr2=(const float*)d_in[11], *br2=(const float*)d_in[12];
    const float *att2=(const float*)d_in[13],*b2=(const float*)d_in[14];
    const float *Wl3=(const float*)d_in[15], *bl3=(const float*)d_in[16];
    const float *Wr3=(const float*)d_in[17], *br3=(const float*)d_in[18];
    const float *att3=(const float*)d_in[19],*b3=(const float*)d_in[20];

    float *p_xl, *p_xr, *p_h;
    cudaGetSymbolAddress((void**)&p_xl, g_xl);
    cudaGetSymbolAddress((void**)&p_xr, g_xr);
    cudaGetSymbolAddress((void**)&p_h,  g_h);

    const int gNodeWarp = gridFor((long long)NN * 32);
    const int gLin128   = (NN + 63) / 64;
    const int gLin32    = (NN + 255) / 256;
    const int gPool     = (NN + 255) / 256;

    // ---- CSR (dst-indexed) build
    deg_count_kernel<<<gridFor(NE), TB>>>(ei);
    scan_kernel<<<1, 1024>>>();
    fill_kernel<<<gridFor(ET), TB>>>(ei);

    // ---- layer 1: 8 -> 128 (H=2, C=64)
    linear_dual_kernel<8, 128><<<gLin128, 256>>>(x, Wl1, bl1, Wr1, br1, p_xl, p_xr);
    gat_fused128_kernel<<<gNodeWarp, TB>>>(att1, b1, p_h);

    // ---- layer 2: 128 -> 128 (H=2, C=64)
    linear_dual_kernel<128, 128><<<gLin128, 256>>>(p_h, Wl2, bl2, Wr2, br2, p_xl, p_xr);
    gat_fused128_kernel<<<gNodeWarp, TB>>>(att2, b2, p_h);

    // ---- layer 3: 128 -> 32 (H=1, C=32)
    linear_dual_kernel<128, 32><<<gLin32, 256>>>(p_h, Wl3, bl3, Wr3, br3, p_xl, p_xr);
    gat_fused32_kernel<<<gNodeWarp, TB>>>(att3, b3, p_h);

    // ---- pooling
    pool_init_kernel<<<gridFor(NG * 32), TB>>>();
    pool_accum_kernel<<<gPool, 256>>>(p_h, batch);
    pool_final_kernel<<<gridFor(NG * 64), TB>>>((float*)d_out);
}

// round 12
// speedup vs baseline: 1.0795x; 1.0549x over previous
#include <cuda_runtime.h>
#include <math.h>

// GATv2 x3 + pooling: CSR + offset-softmax fused edge pass (ILP4),
// dual register-tiled linears (+ dedicated 8->128 kernel), SMEM pooling.
namespace {
constexpr int NN = 50000;
constexpr int NE = 800000;
constexpr int ET = NE + NN;
constexpr int NG = 16;
constexpr int TB = 256;
}

// ---------------- scratch ---------------------------------------------------
__device__ __align__(16) float g_xl[(size_t)NN * 128];
__device__ __align__(16) float g_xr[(size_t)NN * 128];
__device__ __align__(16) float g_h[(size_t)NN * 128];
__device__ int g_deg[NN];            // zero at load; re-zeroed in fill
__device__ int g_rowptr[NN + 1];
__device__ int g_cur[NN];
__device__ int g_csrc[ET];
__device__ float g_psum[NG * 32];
__device__ float g_pmax[NG * 32];
__device__ float g_cntf[NG];

__device__ __forceinline__ void atomicMaxF(float* a, float v) {
    if (v >= 0.f) atomicMax((int*)a, __float_as_int(v));
    else          atomicMin((unsigned int*)a, __float_as_uint(v));
}

// ---------------- CSR build -------------------------------------------------
__global__ void deg_count_kernel(const int* __restrict__ ei) {
    int e = blockIdx.x * blockDim.x + threadIdx.x;
    if (e < NE) atomicAdd(&g_deg[ei[NE + e]], 1);
}
__global__ void scan_kernel() {
    __shared__ int part[1024];
    const int tid = threadIdx.x;
    const int chunk = (NN + 1023) / 1024;
    const int beg = tid * chunk;
    const int end = min(beg + chunk, NN);
    int s = 0;
    for (int i = beg; i < end; i++) s += g_deg[i] + 1;   // +1 self loop
    part[tid] = s;
    __syncthreads();
    if (tid == 0) {
        int run = 0;
        for (int i = 0; i < 1024; i++) { int t = part[i]; part[i] = run; run += t; }
    }
    __syncthreads();
    int run = part[tid];
    for (int i = beg; i < end; i++) {
        g_rowptr[i] = run;
        g_cur[i] = run;
        run += g_deg[i] + 1;
    }
    if (tid == 0) g_rowptr[NN] = ET;
}
__global__ void fill_kernel(const int* __restrict__ ei) {
    int e = blockIdx.x * blockDim.x + threadIdx.x;
    if (e < NN) g_deg[e] = 0;        // re-zero for next replay
    if (e >= ET) return;
    int src, dst;
    if (e < NE) { src = ei[e]; dst = ei[NE + e]; }
    else        { src = e - NE; dst = src; }
    int pos = atomicAdd(&g_cur[dst], 1);
    g_csrc[pos] = src;
}

// ---------------- dedicated 8 -> 128 dual linear ----------------------------
// one thread per (node, 8-output group): 16 acc regs, W in SMEM, high occ.
__global__ __launch_bounds__(256)
void linear8_dual_kernel(const float* __restrict__ X,
                         const float* __restrict__ Wl, const float* __restrict__ Bl,
                         const float* __restrict__ Wr, const float* __restrict__ Br,
                         float* __restrict__ Yl, float* __restrict__ Yr) {
    __shared__ float Wsl[8][128];
    __shared__ float Wsr[8][128];
    const int tid = threadIdx.x;
    for (int i = tid; i < 8 * 128 / 4; i += 256) {
        ((float4*)&Wsl[0][0])[i] = ((const float4*)Wl)[i];
        ((float4*)&Wsr[0][0])[i] = ((const float4*)Wr)[i];
    }
    __syncthreads();

    const int gid  = blockIdx.x * 256 + tid;
    const int node = gid >> 4;
    if (node >= NN) return;
    const int og = gid & 15;            // 8 outputs: [og*8, og*8+8)

    const float4 x0 = *(const float4*)(X + (size_t)node * 8);
    const float4 x1 = *(const float4*)(X + (size_t)node * 8 + 4);
    const float xn[8] = {x0.x, x0.y, x0.z, x0.w, x1.x, x1.y, x1.z, x1.w};

    float4 al0 = ((const float4*)(Bl + og * 8))[0];
    float4 al1 = ((const float4*)(Bl + og * 8))[1];
    float4 ar0 = ((const float4*)(Br + og * 8))[0];
    float4 ar1 = ((const float4*)(Br + og * 8))[1];
#pragma unroll
    for (int k = 0; k < 8; k++) {
        const float4 wl0 = ((const float4*)&Wsl[k][og * 8])[0];
        const float4 wl1 = ((const float4*)&Wsl[k][og * 8])[1];
        const float4 wr0 = ((const float4*)&Wsr[k][og * 8])[0];
        const float4 wr1 = ((const float4*)&Wsr[k][og * 8])[1];
        al0.x += xn[k] * wl0.x; al0.y += xn[k] * wl0.y;
        al0.z += xn[k] * wl0.z; al0.w += xn[k] * wl0.w;
        al1.x += xn[k] * wl1.x; al1.y += xn[k] * wl1.y;
        al1.z += xn[k] * wl1.z; al1.w += xn[k] * wl1.w;
        ar0.x += xn[k] * wr0.x; ar0.y += xn[k] * wr0.y;
        ar0.z += xn[k] * wr0.z; ar0.w += xn[k] * wr0.w;
        ar1.x += xn[k] * wr1.x; ar1.y += xn[k] * wr1.y;
        ar1.z += xn[k] * wr1.z; ar1.w += xn[k] * wr1.w;
    }
    ((float4*)(Yl + (size_t)node * 128 + og * 8))[0] = al0;
    ((float4*)(Yl + (size_t)node * 128 + og * 8))[1] = al1;
    ((float4*)(Yr + (size_t)node * 128 + og * 8))[0] = ar0;
    ((float4*)(Yr + (size_t)node * 128 + og * 8))[1] = ar1;
}

// ---------------- dual linear: Yl = X@Wl+Bl, Yr = X@Wr+Br -------------------
template<int IN, int OUT>
__global__ __launch_bounds__(256)
void linear_dual_kernel(const float* __restrict__ X,
                        const float* __restrict__ Wl, const float* __restrict__ Bl,
                        const float* __restrict__ Wr, const float* __restrict__ Br,
                        float* __restrict__ Yl, float* __restrict__ Yr) {
    constexpr int TO  = OUT / 8;
    constexpr int NGR = 256 / TO;
    constexpr int NPB = NGR * 4;
    constexpr int KT  = (IN < 32) ? IN : 32;

    __shared__ float Xs[KT][NPB + 4];
    __shared__ float Wsl[KT][OUT];
    __shared__ float Wsr[KT][OUT];

    const int tid = threadIdx.x;
    const int og  = tid % TO;
    const int ng  = tid / TO;
    const int nb  = blockIdx.x * NPB;

    float accl[4][8], accr[4][8];
#pragma unroll
    for (int i = 0; i < 4; i++)
#pragma unroll
        for (int j = 0; j < 8; j++) { accl[i][j] = 0.f; accr[i][j] = 0.f; }

    for (int kt = 0; kt < IN; kt += KT) {
        __syncthreads();
        for (int idx = tid; idx < KT * OUT / 4; idx += 256) {
            const int k = idx / (OUT / 4), o4 = idx % (OUT / 4);
            ((float4*)Wsl[k])[o4] = ((const float4*)(Wl + (size_t)(kt + k) * OUT))[o4];
            ((float4*)Wsr[k])[o4] = ((const float4*)(Wr + (size_t)(kt + k) * OUT))[o4];
        }
        for (int idx = tid; idx < NPB * (KT / 4); idx += 256) {
            const int ni = idx / (KT / 4), f4 = idx % (KT / 4);
            const int gn = nb + ni;
            float4 xv = make_float4(0.f, 0.f, 0.f, 0.f);
            if (gn < NN)
                xv = ((const float4*)(X + (size_t)gn * IN + kt))[f4];
            Xs[f4 * 4 + 0][ni] = xv.x;
            Xs[f4 * 4 + 1][ni] = xv.y;
            Xs[f4 * 4 + 2][ni] = xv.z;
            Xs[f4 * 4 + 3][ni] = xv.w;
        }
        __syncthreads();
#pragma unroll
        for (int k = 0; k < KT; k++) {
            float xv[4];
#pragma unroll
            for (int i = 0; i < 4; i++) xv[i] = Xs[k][ng * 4 + i];
            const float4 wl0 = ((const float4*)&Wsl[k][og * 8])[0];
            const float4 wl1 = ((const float4*)&Wsl[k][og * 8])[1];
            const float4 wr0 = ((const float4*)&Wsr[k][og * 8])[0];
            const float4 wr1 = ((const float4*)&Wsr[k][og * 8])[1];
#pragma unroll
            for (int i = 0; i < 4; i++) {
                accl[i][0] += xv[i] * wl0.x; accl[i][1] += xv[i] * wl0.y;
                accl[i][2] += xv[i] * wl0.z; accl[i][3] += xv[i] * wl0.w;
                accl[i][4] += xv[i] * wl1.x; accl[i][5] += xv[i] * wl1.y;
                accl[i][6] += xv[i] * wl1.z; accl[i][7] += xv[i] * wl1.w;
                accr[i][0] += xv[i] * wr0.x; accr[i][1] += xv[i] * wr0.y;
                accr[i][2] += xv[i] * wr0.z; accr[i][3] += xv[i] * wr0.w;
                accr[i][4] += xv[i] * wr1.x; accr[i][5] += xv[i] * wr1.y;
                accr[i][6] += xv[i] * wr1.z; accr[i][7] += xv[i] * wr1.w;
            }
        }
    }

    const float4 bl0 = ((const float4*)(Bl + og * 8))[0];
    const float4 bl1 = ((const float4*)(Bl + og * 8))[1];
    const float4 br0 = ((const float4*)(Br + og * 8))[0];
    const float4 br1 = ((const float4*)(Br + og * 8))[1];
#pragma unroll
    for (int i = 0; i < 4; i++) {
        const int node = nb + ng * 4 + i;
        if (node >= NN) continue;
        float4 o;
        o = make_float4(accl[i][0]+bl0.x, accl[i][1]+bl0.y, accl[i][2]+bl0.z, accl[i][3]+bl0.w);
        ((float4*)(Yl + (size_t)node * OUT + og * 8))[0] = o;
        o = make_float4(accl[i][4]+bl1.x, accl[i][5]+bl1.y, accl[i][6]+bl1.z, accl[i][7]+bl1.w);
        ((float4*)(Yl + (size_t)node * OUT + og * 8))[1] = o;
        o = make_float4(accr[i][0]+br0.x, accr[i][1]+br0.y, accr[i][2]+br0.z, accr[i][3]+br0.w);
        ((float4*)(Yr + (size_t)node * OUT + og * 8))[0] = o;
        o = make_float4(accr[i][4]+br1.x, accr[i][5]+br1.y, accr[i][6]+br1.z, accr[i][7]+br1.w);
        ((float4*)(Yr + (size_t)node * OUT + og * 8))[1] = o;
    }
}

// ---------------- fused GATv2 edge pass (CT=128, H=2), warp/dst, ILP4 -------
// offset softmax: w = exp(s - s_self); shift-invariance makes this exact.
__global__ void gat_fused128_kernel(const float* __restrict__ att,
                                    const float* __restrict__ B,
                                    float* __restrict__ out) {
    const int node = (blockIdx.x * blockDim.x + threadIdx.x) >> 5;
    if (node >= NN) return;
    const int lane = threadIdx.x & 31;

    const float4 xrv  = *(const float4*)(g_xr + (size_t)node * 128 + lane * 4);
    const float4 attv = *(const float4*)(att + lane * 4);

    float s_self;
    {
        const float4 xlv = *(const float4*)(g_xl + (size_t)node * 128 + lane * 4);
        float t, sc = 0.f;
        t = xlv.x + xrv.x; t = t > 0.f ? t : 0.2f * t; sc += t * attv.x;
        t = xlv.y + xrv.y; t = t > 0.f ? t : 0.2f * t; sc += t * attv.y;
        t = xlv.z + xrv.z; t = t > 0.f ? t : 0.2f * t; sc += t * attv.z;
        t = xlv.w + xrv.w; t = t > 0.f ? t : 0.2f * t; sc += t * attv.w;
#pragma unroll
        for (int off = 1; off <= 8; off <<= 1)
            sc += __shfl_xor_sync(0xffffffffu, sc, off);
        s_self = sc;
    }

    int p  = g_rowptr[node];
    const int pe = g_rowptr[node + 1];

    float  dd[4] = {0.f, 0.f, 0.f, 0.f};
    float4 A[4];
#pragma unroll
    for (int j = 0; j < 4; j++) A[j] = make_float4(0.f, 0.f, 0.f, 0.f);

    for (; p + 3 < pe; p += 4) {
        int s[4];
#pragma unroll
        for (int j = 0; j < 4; j++) s[j] = g_csrc[p + j];
        float4 a[4];
#pragma unroll
        for (int j = 0; j < 4; j++)
            a[j] = *(const float4*)(g_xl + (size_t)s[j] * 128 + lane * 4);

        float pp[4];
#pragma unroll
        for (int j = 0; j < 4; j++) {
            float t, sc = 0.f;
            t = a[j].x + xrv.x; t = t > 0.f ? t : 0.2f * t; sc += t * attv.x;
            t = a[j].y + xrv.y; t = t > 0.f ? t : 0.2f * t; sc += t * attv.y;
            t = a[j].z + xrv.z; t = t > 0.f ? t : 0.2f * t; sc += t * attv.z;
            t = a[j].w + xrv.w; t = t > 0.f ? t : 0.2f * t; sc += t * attv.w;
            pp[j] = sc;
        }
#pragma unroll
        for (int off = 1; off <= 8; off <<= 1)
#pragma unroll
            for (int j = 0; j < 4; j++)
                pp[j] += __shfl_xor_sync(0xffffffffu, pp[j], off);
#pragma unroll
        for (int j = 0; j < 4; j++) {
            const float w = __expf(pp[j] - s_self);
            dd[j] += w;
            A[j].x += w * a[j].x;
            A[j].y += w * a[j].y;
            A[j].z += w * a[j].z;
            A[j].w += w * a[j].w;
        }
    }
    for (; p < pe; ++p) {
        const int s0 = g_csrc[p];
        const float4 a0 = *(const float4*)(g_xl + (size_t)s0 * 128 + lane * 4);
        float t, p0 = 0.f;
        t = a0.x + xrv.x; t = t > 0.f ? t : 0.2f * t; p0 += t * attv.x;
        t = a0.y + xrv.y; t = t > 0.f ? t : 0.2f * t; p0 += t * attv.y;
        t = a0.z + xrv.z; t = t > 0.f ? t : 0.2f * t; p0 += t * attv.z;
        t = a0.w + xrv.w; t = t > 0.f ? t : 0.2f * t; p0 += t * attv.w;
#pragma unroll
        for (int off = 1; off <= 8; off <<= 1)
            p0 += __shfl_xor_sync(0xffffffffu, p0, off);
        const float w = __expf(p0 - s_self);
        dd[0] += w;
        A[0].x += w * a0.x;
        A[0].y += w * a0.y;
        A[0].z += w * a0.z;
        A[0].w += w * a0.w;
    }

    const float d = dd[0] + dd[1] + dd[2] + dd[3];
    float4 acc;
    acc.x = A[0].x + A[1].x + A[2].x + A[3].x;
    acc.y = A[0].y + A[1].y + A[2].y + A[3].y;
    acc.z = A[0].z + A[1].z + A[2].z + A[3].z;
    acc.w = A[0].w + A[1].w + A[2].w + A[3].w;

    const float inv = 1.f / d;
    const float4 bv = *(const float4*)(B + lane * 4);
    float4 o;
    o.x = acc.x * inv + bv.x; o.x = o.x > 0.f ? o.x : expm1f(o.x);
    o.y = acc.y * inv + bv.y; o.y = o.y > 0.f ? o.y : expm1f(o.y);
    o.z = acc.z * inv + bv.z; o.z = o.z > 0.f ? o.z : expm1f(o.z);
    o.w = acc.w * inv + bv.w; o.w = o.w > 0.f ? o.w : expm1f(o.w);
    *(float4*)(out + (size_t)node * 128 + lane * 4) = o;
}

// ---------------- fused GATv2 edge pass (CT=32, H=1), warp/dst, ILP4 --------
__global__ void gat_fused32_kernel(const float* __restrict__ att,
                                   const float* __restrict__ B,
                                   float* __restrict__ out) {
    const int node = (blockIdx.x * blockDim.x + threadIdx.x) >> 5;
    if (node >= NN) return;
    const int lane = threadIdx.x & 31;

    const float xrv  = g_xr[(size_t)node * 32 + lane];
    const float attv = att[lane];

    float s_self;
    {
        const float xlv = g_xl[(size_t)node * 32 + lane];
        float t = xlv + xrv; t = t > 0.f ? t : 0.2f * t;
        float sc = t * attv;
#pragma unroll
        for (int off = 1; off <= 16; off <<= 1)
            sc += __shfl_xor_sync(0xffffffffu, sc, off);
        s_self = sc;
    }

    int p  = g_rowptr[node];
    const int pe = g_rowptr[node + 1];

    float dd[4] = {0.f, 0.f, 0.f, 0.f};
    float A[4] = {0.f, 0.f, 0.f, 0.f};

    for (; p + 3 < pe; p += 4) {
        float a[4], pp[4];
#pragma unroll
        for (int j = 0; j < 4; j++) {
            const int s = g_csrc[p + j];
            a[j] = g_xl[(size_t)s * 32 + lane];
            float t = a[j] + xrv; t = t > 0.f ? t : 0.2f * t;
            pp[j] = t * attv;
        }
#pragma unroll
        for (int off = 1; off <= 16; off <<= 1)
#pragma unroll
            for (int j = 0; j < 4; j++)
                pp[j] += __shfl_xor_sync(0xffffffffu, pp[j], off);
#pragma unroll
        for (int j = 0; j < 4; j++) {
            const float w = __expf(pp[j] - s_self);
            dd[j] += w; A[j] += w * a[j];
        }
    }
    for (; p < pe; ++p) {
        const int s = g_csrc[p];
        const float a0 = g_xl[(size_t)s * 32 + lane];
        float t = a0 + xrv; t = t > 0.f ? t : 0.2f * t;
        float p0 = t * attv;
#pragma unroll
        for (int off = 1; off <= 16; off <<= 1)
            p0 += __shfl_xor_sync(0xffffffffu, p0, off);
        const float w = __expf(p0 - s_self);
        dd[0] += w; A[0] += w * a0;
    }

    const float d = dd[0] + dd[1] + dd[2] + dd[3];
    const float acc = A[0] + A[1] + A[2] + A[3];

    float o = acc / d + B[lane];
    o = o > 0.f ? o : expm1f(o);
    out[(size_t)node * 32 + lane] = o;
}

// ---------------- pooling ----------------------------------------------------
__global__ void pool_init_kernel() {
    int i = blockIdx.x * blockDim.x + threadIdx.x;
    if (i < NG * 32) { g_psum[i] = 0.f; g_pmax[i] = -INFINITY; }
    if (i < NG) g_cntf[i] = 0.f;
}

__global__ __launch_bounds__(256)
void pool_accum_kernel(const float* __restrict__ h,
                       const int* __restrict__ batch) {
    __shared__ float ssum[NG * 32];
    __shared__ float smax[NG * 32];
    __shared__ int   scnt[NG];
    const int tid = threadIdx.x;
    for (int i = tid; i < NG * 32; i += 256) { ssum[i] = 0.f; smax[i] = -INFINITY; }
    if (tid < NG) scnt[tid] = 0;
    __syncthreads();

    const int warp = tid >> 5, lane = tid & 31;
    const int nbase = blockIdx.x * 256 + warp * 32;
#pragma unroll 4
    for (int i = 0; i < 32; i++) {
        const int node = nbase + i;
        if (node >= NN) break;
        const int g = batch[node];
        const float v = h[(size_t)node * 32 + lane];
        atomicAdd(&ssum[g * 32 + lane], v);
        atomicMaxF(&smax[g * 32 + lane], v);
        if (lane == 0) atomicAdd(&scnt[g], 1);
    }
    __syncthreads();

    for (int i = tid; i < NG * 32; i += 256) {
        if (ssum[i] != 0.f) atomicAdd(&g_psum[i], ssum[i]);
        if (smax[i] != -INFINITY) atomicMaxF(&g_pmax[i], smax[i]);
    }
    if (tid < NG && scnt[tid] > 0) atomicAdd(&g_cntf[tid], (float)scnt[tid]);
}

__global__ void pool_final_kernel(float* __restrict__ out) {
    const int i = blockIdx.x * blockDim.x + threadIdx.x;
    if (i >= NG * 64) return;
    const int g = i / 64, c = i % 64;
    out[i] = (c < 32) ? g_psum[g * 32 + c] / g_cntf[g]
                      : g_pmax[g * 32 + (c - 32)];
}

// ---------------- launch ------------------------------------------------------
static inline int gridFor(long long n) { return (int)((n + TB - 1) / TB); }

extern "C" void kernel_launch(void* const* d_in, const int* in_sizes, int n_in,
                              void* d_out, int out_size) {
    const float* x     = (const float*)d_in[0];
    const int*   ei    = (const int*)d_in[1];
    const int*   batch = (const int*)d_in[2];
    const float *Wl1=(const float*)d_in[3],  *bl1=(const float*)d_in[4];
    const float *Wr1=(const float*)d_in[5],  *br1=(const float*)d_in[6];
    const float *att1=(const float*)d_in[7], *b1=(const float*)d_in[8];
    const float *Wl2=(const float*)d_in[9],  *bl2=(const float*)d_in[10];
    const float *Wr2=(const float*)d_in[11], *br2=(const float*)d_in[12];
    const float *att2=(const float*)d_in[13],*b2=(const float*)d_in[14];
    const float *Wl3=(const float*)d_in[15], *bl3=(const float*)d_in[16];
    const float *Wr3=(const float*)d_in[17], *br3=(const float*)d_in[18];
    const float *att3=(const float*)d_in[19],*b3=(const float*)d_in[20];

    float *p_xl, *p_xr, *p_h;
    cudaGetSymbolAddress((void**)&p_xl, g_xl);
    cudaGetSymbolAddress((void**)&p_xr, g_xr);
    cudaGetSymbolAddress((void**)&p_h,  g_h);

    const int gNodeWarp = gridFor((long long)NN * 32);
    const int gLin8     = gridFor((long long)NN * 16);
    const int gLin128   = (NN + 63) / 64;
    const int gLin32    = (NN + 255) / 256;
    const int gPool     = (NN + 255) / 256;

    // ---- CSR (dst-indexed) build
    deg_count_kernel<<<gridFor(NE), TB>>>(ei);
    scan_kernel<<<1, 1024>>>();
    fill_kernel<<<gridFor(ET), TB>>>(ei);

    // ---- layer 1: 8 -> 128 (H=2, C=64)
    linear8_dual_kernel<<<gLin8, 256>>>(x, Wl1, bl1, Wr1, br1, p_xl, p_xr);
    gat_fused128_kernel<<<gNodeWarp, TB>>>(att1, b1, p_h);

    // ---- layer 2: 128 -> 128 (H=2, C=64)
    linear_dual_kernel<128, 128><<<gLin128, 256>>>(p_h, Wl2, bl2, Wr2, br2, p_xl, p_xr);
    gat_fused128_kernel<<<gNodeWarp, TB>>>(att2, b2, p_h);

    // ---- layer 3: 128 -> 32 (H=1, C=32)
    linear_dual_kernel<128, 32><<<gLin32, 256>>>(p_h, Wl3, bl3, Wr3, br3, p_xl, p_xr);
    gat_fused32_kernel<<<gNodeWarp, TB>>>(att3, b3, p_h);

    // ---- pooling
    pool_init_kernel<<<gridFor(NG * 32), TB>>>();
    pool_accum_kernel<<<gPool, 256>>>(p_h, batch);
    pool_final_kernel<<<gridFor(NG * 64), TB>>>((float*)d_out);
}

// round 13
// speedup vs baseline: 1.1168x; 1.0345x over previous
#include <cuda_runtime.h>
#include <math.h>

// GATv2 x3 + pooling: CSR (parallel scan) + offset-softmax fused edge pass
// (ILP4), dual register-tiled linears, SMEM pooling, stream-forked layer-1
// linear overlapped with CSR build.
namespace {
constexpr int NN = 50000;
constexpr int NE = 800000;
constexpr int ET = NE + NN;
constexpr int NG = 16;
constexpr int TB = 256;
}

// ---------------- scratch ---------------------------------------------------
__device__ __align__(16) float g_xl[(size_t)NN * 128];
__device__ __align__(16) float g_xr[(size_t)NN * 128];
__device__ __align__(16) float g_h[(size_t)NN * 128];
__device__ int g_deg[NN];            // zero at load; re-zeroed in fill
__device__ int g_rowptr[NN + 1];
__device__ int g_cur[NN];
__device__ int g_csrc[ET];
__device__ float g_psum[NG * 32];
__device__ float g_pmax[NG * 32];
__device__ float g_cntf[NG];

__device__ __forceinline__ void atomicMaxF(float* a, float v) {
    if (v >= 0.f) atomicMax((int*)a, __float_as_int(v));
    else          atomicMin((unsigned int*)a, __float_as_uint(v));
}

// ---------------- CSR build -------------------------------------------------
__global__ void deg_count_kernel(const int* __restrict__ ei) {
    int e = blockIdx.x * blockDim.x + threadIdx.x;
    if (e < NE) atomicAdd(&g_deg[ei[NE + e]], 1);
}
__global__ void scan_kernel() {
    __shared__ int part[1024];
    const int tid = threadIdx.x;
    const int chunk = (NN + 1023) / 1024;
    const int beg = tid * chunk;
    const int end = min(beg + chunk, NN);
    int s = 0;
    for (int i = beg; i < end; i++) s += g_deg[i] + 1;   // +1 self loop
    part[tid] = s;
    __syncthreads();
    // Hillis-Steele inclusive scan over 1024 partials
#pragma unroll
    for (int off = 1; off < 1024; off <<= 1) {
        int add = (tid >= off) ? part[tid - off] : 0;
        __syncthreads();
        part[tid] += add;
        __syncthreads();
    }
    int run = (tid == 0) ? 0 : part[tid - 1];            // exclusive
    for (int i = beg; i < end; i++) {
        g_rowptr[i] = run;
        g_cur[i] = run;
        run += g_deg[i] + 1;
    }
    if (tid == 0) g_rowptr[NN] = ET;
}
__global__ void fill_kernel(const int* __restrict__ ei) {
    int e = blockIdx.x * blockDim.x + threadIdx.x;
    if (e < NN) g_deg[e] = 0;        // re-zero for next replay
    if (e >= ET) return;
    int src, dst;
    if (e < NE) { src = ei[e]; dst = ei[NE + e]; }
    else        { src = e - NE; dst = src; }
    int pos = atomicAdd(&g_cur[dst], 1);
    g_csrc[pos] = src;
}

// ---------------- dual linear: Yl = X@Wl+Bl, Yr = X@Wr+Br -------------------
template<int IN, int OUT>
__global__ __launch_bounds__(256)
void linear_dual_kernel(const float* __restrict__ X,
                        const float* __restrict__ Wl, const float* __restrict__ Bl,
                        const float* __restrict__ Wr, const float* __restrict__ Br,
                        float* __restrict__ Yl, float* __restrict__ Yr) {
    constexpr int TO  = OUT / 8;
    constexpr int NGR = 256 / TO;
    constexpr int NPB = NGR * 4;
    constexpr int KT  = (IN < 32) ? IN : 32;

    __shared__ float Xs[KT][NPB + 4];
    __shared__ float Wsl[KT][OUT];
    __shared__ float Wsr[KT][OUT];

    const int tid = threadIdx.x;
    const int og  = tid % TO;
    const int ng  = tid / TO;
    const int nb  = blockIdx.x * NPB;

    float accl[4][8], accr[4][8];
#pragma unroll
    for (int i = 0; i < 4; i++)
#pragma unroll
        for (int j = 0; j < 8; j++) { accl[i][j] = 0.f; accr[i][j] = 0.f; }

    for (int kt = 0; kt < IN; kt += KT) {
        __syncthreads();
        for (int idx = tid; idx < KT * OUT / 4; idx += 256) {
            const int k = idx / (OUT / 4), o4 = idx % (OUT / 4);
            ((float4*)Wsl[k])[o4] = ((const float4*)(Wl + (size_t)(kt + k) * OUT))[o4];
            ((float4*)Wsr[k])[o4] = ((const float4*)(Wr + (size_t)(kt + k) * OUT))[o4];
        }
        for (int idx = tid; idx < NPB * (KT / 4); idx += 256) {
            const int ni = idx / (KT / 4), f4 = idx % (KT / 4);
            const int gn = nb + ni;
            float4 xv = make_float4(0.f, 0.f, 0.f, 0.f);
            if (gn < NN)
                xv = ((const float4*)(X + (size_t)gn * IN + kt))[f4];
            Xs[f4 * 4 + 0][ni] = xv.x;
            Xs[f4 * 4 + 1][ni] = xv.y;
            Xs[f4 * 4 + 2][ni] = xv.z;
            Xs[f4 * 4 + 3][ni] = xv.w;
        }
        __syncthreads();
#pragma unroll
        for (int k = 0; k < KT; k++) {
            float xv[4];
#pragma unroll
            for (int i = 0; i < 4; i++) xv[i] = Xs[k][ng * 4 + i];
            const float4 wl0 = ((const float4*)&Wsl[k][og * 8])[0];
            const float4 wl1 = ((const float4*)&Wsl[k][og * 8])[1];
            const float4 wr0 = ((const float4*)&Wsr[k][og * 8])[0];
            const float4 wr1 = ((const float4*)&Wsr[k][og * 8])[1];
#pragma unroll
            for (int i = 0; i < 4; i++) {
                accl[i][0] += xv[i] * wl0.x; accl[i][1] += xv[i] * wl0.y;
                accl[i][2] += xv[i] * wl0.z; accl[i][3] += xv[i] * wl0.w;
                accl[i][4] += xv[i] * wl1.x; accl[i][5] += xv[i] * wl1.y;
                accl[i][6] += xv[i] * wl1.z; accl[i][7] += xv[i] * wl1.w;
                accr[i][0] += xv[i] * wr0.x; accr[i][1] += xv[i] * wr0.y;
                accr[i][2] += xv[i] * wr0.z; accr[i][3] += xv[i] * wr0.w;
                accr[i][4] += xv[i] * wr1.x; accr[i][5] += xv[i] * wr1.y;
                accr[i][6] += xv[i] * wr1.z; accr[i][7] += xv[i] * wr1.w;
            }
        }
    }

    const float4 bl0 = ((const float4*)(Bl + og * 8))[0];
    const float4 bl1 = ((const float4*)(Bl + og * 8))[1];
    const float4 br0 = ((const float4*)(Br + og * 8))[0];
    const float4 br1 = ((const float4*)(Br + og * 8))[1];
#pragma unroll
    for (int i = 0; i < 4; i++) {
        const int node = nb + ng * 4 + i;
        if (node >= NN) continue;
        float4 o;
        o = make_float4(accl[i][0]+bl0.x, accl[i][1]+bl0.y, accl[i][2]+bl0.z, accl[i][3]+bl0.w);
        ((float4*)(Yl + (size_t)node * OUT + og * 8))[0] = o;
        o = make_float4(accl[i][4]+bl1.x, accl[i][5]+bl1.y, accl[i][6]+bl1.z, accl[i][7]+bl1.w);
        ((float4*)(Yl + (size_t)node * OUT + og * 8))[1] = o;
        o = make_float4(accr[i][0]+br0.x, accr[i][1]+br0.y, accr[i][2]+br0.z, accr[i][3]+br0.w);
        ((float4*)(Yr + (size_t)node * OUT + og * 8))[0] = o;
        o = make_float4(accr[i][4]+br1.x, accr[i][5]+br1.y, accr[i][6]+br1.z, accr[i][7]+br1.w);
        ((float4*)(Yr + (size_t)node * OUT + og * 8))[1] = o;
    }
}

// ---------------- fused GATv2 edge pass (CT=128, H=2), warp/dst, ILP4 -------
__global__ void gat_fused128_kernel(const float* __restrict__ att,
                                    const float* __restrict__ B,
                                    float* __restrict__ out) {
    const int node = (blockIdx.x * blockDim.x + threadIdx.x) >> 5;
    if (node >= NN) return;
    const int lane = threadIdx.x & 31;

    const float4 xrv  = *(const float4*)(g_xr + (size_t)node * 128 + lane * 4);
    const float4 attv = *(const float4*)(att + lane * 4);

    float s_self;
    {
        const float4 xlv = *(const float4*)(g_xl + (size_t)node * 128 + lane * 4);
        float t, sc = 0.f;
        t = xlv.x + xrv.x; t = t > 0.f ? t : 0.2f * t; sc += t * attv.x;
        t = xlv.y + xrv.y; t = t > 0.f ? t : 0.2f * t; sc += t * attv.y;
        t = xlv.z + xrv.z; t = t > 0.f ? t : 0.2f * t; sc += t * attv.z;
        t = xlv.w + xrv.w; t = t > 0.f ? t : 0.2f * t; sc += t * attv.w;
#pragma unroll
        for (int off = 1; off <= 8; off <<= 1)
            sc += __shfl_xor_sync(0xffffffffu, sc, off);
        s_self = sc;
    }

    int p  = g_rowptr[node];
    const int pe = g_rowptr[node + 1];

    float  dd[4] = {0.f, 0.f, 0.f, 0.f};
    float4 A[4];
#pragma unroll
    for (int j = 0; j < 4; j++) A[j] = make_float4(0.f, 0.f, 0.f, 0.f);

    for (; p + 3 < pe; p += 4) {
        int s[4];
#pragma unroll
        for (int j = 0; j < 4; j++) s[j] = g_csrc[p + j];
        float4 a[4];
#pragma unroll
        for (int j = 0; j < 4; j++)
            a[j] = *(const float4*)(g_xl + (size_t)s[j] * 128 + lane * 4);

        float pp[4];
#pragma unroll
        for (int j = 0; j < 4; j++) {
            float t, sc = 0.f;
            t = a[j].x + xrv.x; t = t > 0.f ? t : 0.2f * t; sc += t * attv.x;
            t = a[j].y + xrv.y; t = t > 0.f ? t : 0.2f * t; sc += t * attv.y;
            t = a[j].z + xrv.z; t = t > 0.f ? t : 0.2f * t; sc += t * attv.z;
            t = a[j].w + xrv.w; t = t > 0.f ? t : 0.2f * t; sc += t * attv.w;
            pp[j] = sc;
        }
#pragma unroll
        for (int off = 1; off <= 8; off <<= 1)
#pragma unroll
            for (int j = 0; j < 4; j++)
                pp[j] += __shfl_xor_sync(0xffffffffu, pp[j], off);
#pragma unroll
        for (int j = 0; j < 4; j++) {
            const float w = __expf(pp[j] - s_self);
            dd[j] += w;
            A[j].x += w * a[j].x;
            A[j].y += w * a[j].y;
            A[j].z += w * a[j].z;
            A[j].w += w * a[j].w;
        }
    }
    for (; p < pe; ++p) {
        const int s0 = g_csrc[p];
        const float4 a0 = *(const float4*)(g_xl + (size_t)s0 * 128 + lane * 4);
        float t, p0 = 0.f;
        t = a0.x + xrv.x; t = t > 0.f ? t : 0.2f * t; p0 += t * attv.x;
        t = a0.y + xrv.y; t = t > 0.f ? t : 0.2f * t; p0 += t * attv.y;
        t = a0.z + xrv.z; t = t > 0.f ? t : 0.2f * t; p0 += t * attv.z;
        t = a0.w + xrv.w; t = t > 0.f ? t : 0.2f * t; p0 += t * attv.w;
#pragma unroll
        for (int off = 1; off <= 8; off <<= 1)
            p0 += __shfl_xor_sync(0xffffffffu, p0, off);
        const float w = __expf(p0 - s_self);
        dd[0] += w;
        A[0].x += w * a0.x;
        A[0].y += w * a0.y;
        A[0].z += w * a0.z;
        A[0].w += w * a0.w;
    }

    const float d = dd[0] + dd[1] + dd[2] + dd[3];
    float4 acc;
    acc.x = A[0].x + A[1].x + A[2].x + A[3].x;
    acc.y = A[0].y + A[1].y + A[2].y + A[3].y;
    acc.z = A[0].z + A[1].z + A[2].z + A[3].z;
    acc.w = A[0].w + A[1].w + A[2].w + A[3].w;

    const float inv = 1.f / d;
    const float4 bv = *(const float4*)(B + lane * 4);
    float4 o;
    o.x = acc.x * inv + bv.x; o.x = o.x > 0.f ? o.x : expm1f(o.x);
    o.y = acc.y * inv + bv.y; o.y = o.y > 0.f ? o.y : expm1f(o.y);
    o.z = acc.z * inv + bv.z; o.z = o.z > 0.f ? o.z : expm1f(o.z);
    o.w = acc.w * inv + bv.w; o.w = o.w > 0.f ? o.w : expm1f(o.w);
    *(float4*)(out + (size_t)node * 128 + lane * 4) = o;
}

// ---------------- fused GATv2 edge pass (CT=32, H=1), warp/dst, ILP4 --------
__global__ void gat_fused32_kernel(const float* __restrict__ att,
                                   const float* __restrict__ B,
                                   float* __restrict__ out) {
    const int node = (blockIdx.x * blockDim.x + threadIdx.x) >> 5;
    if (node >= NN) return;
    const int lane = threadIdx.x & 31;

    const float xrv  = g_xr[(size_t)node * 32 + lane];
    const float attv = att[lane];

    float s_self;
    {
        const float xlv = g_xl[(size_t)node * 32 + lane];
        float t = xlv + xrv; t = t > 0.f ? t : 0.2f * t;
        float sc = t * attv;
#pragma unroll
        for (int off = 1; off <= 16; off <<= 1)
            sc += __shfl_xor_sync(0xffffffffu, sc, off);
        s_self = sc;
    }

    int p  = g_rowptr[node];
    const int pe = g_rowptr[node + 1];

    float dd[4] = {0.f, 0.f, 0.f, 0.f};
    float A[4] = {0.f, 0.f, 0.f, 0.f};

    for (; p + 3 < pe; p += 4) {
        float a[4], pp[4];
#pragma unroll
        for (int j = 0; j < 4; j++) {
            const int s = g_csrc[p + j];
            a[j] = g_xl[(size_t)s * 32 + lane];
            float t = a[j] + xrv; t = t > 0.f ? t : 0.2f * t;
            pp[j] = t * attv;
        }
#pragma unroll
        for (int off = 1; off <= 16; off <<= 1)
#pragma unroll
            for (int j = 0; j < 4; j++)
                pp[j] += __shfl_xor_sync(0xffffffffu, pp[j], off);
#pragma unroll
        for (int j = 0; j < 4; j++) {
            const float w = __expf(pp[j] - s_self);
            dd[j] += w; A[j] += w * a[j];
        }
    }
    for (; p < pe; ++p) {
        const int s = g_csrc[p];
        const float a0 = g_xl[(size_t)s * 32 + lane];
        float t = a0 + xrv; t = t > 0.f ? t : 0.2f * t;
        float p0 = t * attv;
#pragma unroll
        for (int off = 1; off <= 16; off <<= 1)
            p0 += __shfl_xor_sync(0xffffffffu, p0, off);
        const float w = __expf(p0 - s_self);
        dd[0] += w; A[0] += w * a0;
    }

    const float d = dd[0] + dd[1] + dd[2] + dd[3];
    const float acc = A[0] + A[1] + A[2] + A[3];

    float o = acc / d + B[lane];
    o = o > 0.f ? o : expm1f(o);
    out[(size_t)node * 32 + lane] = o;
}

// ---------------- pooling ----------------------------------------------------
__global__ void pool_init_kernel() {
    int i = blockIdx.x * blockDim.x + threadIdx.x;
    if (i < NG * 32) { g_psum[i] = 0.f; g_pmax[i] = -INFINITY; }
    if (i < NG) g_cntf[i] = 0.f;
}

__global__ __launch_bounds__(256)
void pool_accum_kernel(const float* __restrict__ h,
                       const int* __restrict__ batch) {
    __shared__ float ssum[NG * 32];
    __shared__ float smax[NG * 32];
    __shared__ int   scnt[NG];
    const int tid = threadIdx.x;
    for (int i = tid; i < NG * 32; i += 256) { ssum[i] = 0.f; smax[i] = -INFINITY; }
    if (tid < NG) scnt[tid] = 0;
    __syncthreads();

    const int warp = tid >> 5, lane = tid & 31;
    const int nbase = blockIdx.x * 256 + warp * 32;
#pragma unroll 4
    for (int i = 0; i < 32; i++) {
        const int node = nbase + i;
        if (node >= NN) break;
        const int g = batch[node];
        const float v = h[(size_t)node * 32 + lane];
        atomicAdd(&ssum[g * 32 + lane], v);
        atomicMaxF(&smax[g * 32 + lane], v);
        if (lane == 0) atomicAdd(&scnt[g], 1);
    }
    __syncthreads();

    for (int i = tid; i < NG * 32; i += 256) {
        if (ssum[i] != 0.f) atomicAdd(&g_psum[i], ssum[i]);
        if (smax[i] != -INFINITY) atomicMaxF(&g_pmax[i], smax[i]);
    }
    if (tid < NG && scnt[tid] > 0) atomicAdd(&g_cntf[tid], (float)scnt[tid]);
}

__global__ void pool_final_kernel(float* __restrict__ out) {
    const int i = blockIdx.x * blockDim.x + threadIdx.x;
    if (i >= NG * 64) return;
    const int g = i / 64, c = i % 64;
    out[i] = (c < 32) ? g_psum[g * 32 + c] / g_cntf[g]
                      : g_pmax[g * 32 + (c - 32)];
}

// ---------------- launch ------------------------------------------------------
static inline int gridFor(long long n) { return (int)((n + TB - 1) / TB); }

extern "C" void kernel_launch(void* const* d_in, const int* in_sizes, int n_in,
                              void* d_out, int out_size) {
    const float* x     = (const float*)d_in[0];
    const int*   ei    = (const int*)d_in[1];
    const int*   batch = (const int*)d_in[2];
    const float *Wl1=(const float*)d_in[3],  *bl1=(const float*)d_in[4];
    const float *Wr1=(const float*)d_in[5],  *br1=(const float*)d_in[6];
    const float *att1=(const float*)d_in[7], *b1=(const float*)d_in[8];
    const float *Wl2=(const float*)d_in[9],  *bl2=(const float*)d_in[10];
    const float *Wr2=(const float*)d_in[11], *br2=(const float*)d_in[12];
    const float *att2=(const float*)d_in[13],*b2=(const float*)d_in[14];
    const float *Wl3=(const float*)d_in[15], *bl3=(const float*)d_in[16];
    const float *Wr3=(const float*)d_in[17], *br3=(const float*)d_in[18];
    const float *att3=(const float*)d_in[19],*b3=(const float*)d_in[20];

    float *p_xl, *p_xr, *p_h;
    cudaGetSymbolAddress((void**)&p_xl, g_xl);
    cudaGetSymbolAddress((void**)&p_xr, g_xr);
    cudaGetSymbolAddress((void**)&p_h,  g_h);

    // one-time side-stream + events (host objects; created on the uncaptured
    // correctness call, reused identically on every call thereafter)
    static cudaStream_t s2 = nullptr;
    static cudaEvent_t evFork = nullptr, evJoin = nullptr;
    if (s2 == nullptr) {
        cudaStreamCreateWithFlags(&s2, cudaStreamNonBlocking);
        cudaEventCreateWithFlags(&evFork, cudaEventDisableTiming);
        cudaEventCreateWithFlags(&evJoin, cudaEventDisableTiming);
    }

    const int gNodeWarp = gridFor((long long)NN * 32);
    const int gLin128   = (NN + 63) / 64;
    const int gLin32    = (NN + 255) / 256;
    const int gPool     = (NN + 255) / 256;

    // ---- fork: layer-1 linear on s2, concurrent with CSR build -------------
    cudaEventRecord(evFork, 0);
    cudaStreamWaitEvent(s2, evFork, 0);
    linear_dual_kernel<8, 128><<<gLin128, 256, 0, s2>>>(x, Wl1, bl1, Wr1, br1,
                                                        p_xl, p_xr);
    cudaEventRecord(evJoin, s2);

    // ---- CSR (dst-indexed) build on default stream -------------------------
    deg_count_kernel<<<gridFor(NE), TB>>>(ei);
    scan_kernel<<<1, 1024>>>();
    fill_kernel<<<gridFor(ET), TB>>>(ei);

    // join before first fused pass
    cudaStreamWaitEvent(0, evJoin, 0);

    // ---- layer 1: 8 -> 128 (H=2, C=64)
    gat_fused128_kernel<<<gNodeWarp, TB>>>(att1, b1, p_h);

    // ---- layer 2: 128 -> 128 (H=2, C=64)
    linear_dual_kernel<128, 128><<<gLin128, 256>>>(p_h, Wl2, bl2, Wr2, br2, p_xl, p_xr);
    gat_fused128_kernel<<<gNodeWarp, TB>>>(att2, b2, p_h);

    // ---- layer 3: 128 -> 32 (H=1, C=32)
    linear_dual_kernel<128, 32><<<gLin32, 256>>>(p_h, Wl3, bl3, Wr3, br3, p_xl, p_xr);
    gat_fused32_kernel<<<gNodeWarp, TB>>>(att3, b3, p_h);

    // ---- pooling
    pool_init_kernel<<<gridFor(NG * 32), TB>>>();
    pool_accum_kernel<<<gPool, 256>>>(p_h, batch);
    pool_final_kernel<<<gridFor(NG * 64), TB>>>((float*)d_out);
}

// round 14
// speedup vs baseline: 1.2694x; 1.1367x over previous
#include <cuda_runtime.h>
#include <math.h>

// GATv2 x3 + pooling: CSR (parallel scan) + offset-softmax fused edge pass
// (ILP4), TF32 mma.sync dual linear for 128->128, stream-forked layer-1
// linear + pool_init overlapped with CSR build, SMEM pooling.
namespace {
constexpr int NN = 50000;
constexpr int NE = 800000;
constexpr int ET = NE + NN;
constexpr int NG = 16;
constexpr int TB = 256;
}

// ---------------- scratch ---------------------------------------------------
__device__ __align__(16) float g_xl[(size_t)NN * 128];
__device__ __align__(16) float g_xr[(size_t)NN * 128];
__device__ __align__(16) float g_h[(size_t)NN * 128];
__device__ int g_deg[NN];            // zero at load; re-zeroed in fill
__device__ int g_rowptr[NN + 1];
__device__ int g_cur[NN];
__device__ int g_csrc[ET];
__device__ float g_psum[NG * 32];
__device__ float g_pmax[NG * 32];
__device__ float g_cntf[NG];

__device__ __forceinline__ void atomicMaxF(float* a, float v) {
    if (v >= 0.f) atomicMax((int*)a, __float_as_int(v));
    else          atomicMin((unsigned int*)a, __float_as_uint(v));
}

__device__ __forceinline__ unsigned f2tf32(float x) {
    unsigned u;
    asm("cvt.rna.tf32.f32 %0, %1;" : "=r"(u) : "f"(x));
    return u;
}

// ---------------- CSR build -------------------------------------------------
__global__ void deg_count_kernel(const int* __restrict__ ei) {
    int e = blockIdx.x * blockDim.x + threadIdx.x;
    if (e < NE) atomicAdd(&g_deg[ei[NE + e]], 1);
}
__global__ void scan_kernel() {
    __shared__ int part[1024];
    const int tid = threadIdx.x;
    const int chunk = (NN + 1023) / 1024;
    const int beg = tid * chunk;
    const int end = min(beg + chunk, NN);
    int s = 0;
    for (int i = beg; i < end; i++) s += g_deg[i] + 1;   // +1 self loop
    part[tid] = s;
    __syncthreads();
#pragma unroll
    for (int off = 1; off < 1024; off <<= 1) {
        int add = (tid >= off) ? part[tid - off] : 0;
        __syncthreads();
        part[tid] += add;
        __syncthreads();
    }
    int run = (tid == 0) ? 0 : part[tid - 1];            // exclusive
    for (int i = beg; i < end; i++) {
        g_rowptr[i] = run;
        g_cur[i] = run;
        run += g_deg[i] + 1;
    }
    if (tid == 0) g_rowptr[NN] = ET;
}
__global__ void fill_kernel(const int* __restrict__ ei) {
    int e = blockIdx.x * blockDim.x + threadIdx.x;
    if (e < NN) g_deg[e] = 0;        // re-zero for next replay
    if (e >= ET) return;
    int src, dst;
    if (e < NE) { src = ei[e]; dst = ei[NE + e]; }
    else        { src = e - NE; dst = src; }
    int pos = atomicAdd(&g_cur[dst], 1);
    g_csrc[pos] = src;
}

// ---------------- TF32 mma dual linear: 128 -> 128 x 2 matrices -------------
// block = 256 thr = 8 warps; block tile = 64 nodes x 128 cols x {Wl, Wr}.
// warp w: matrix = w&1, row-tile = w>>2? NO: rt = w>>1 (0..3) -> rows 16.
__global__ __launch_bounds__(256)
void linear_tf32_dual_kernel(const float* __restrict__ X,
                             const float* __restrict__ Wl, const float* __restrict__ Bl,
                             const float* __restrict__ Wr, const float* __restrict__ Br,
                             float* __restrict__ Yl, float* __restrict__ Yr) {
    __shared__ unsigned Ws[2][8][136];   // [matrix][k][n], padded vs bank conflicts
    const int tid  = threadIdx.x;
    const int warp = tid >> 5, lane = tid & 31;
    const int mat  = warp & 1;
    const int rt   = warp >> 1;                  // 0..3
    const int node0 = blockIdx.x * 64 + rt * 16;
    const int gid = lane >> 2;                   // 0..7
    const int tig = lane & 3;                    // 0..3

    float acc[16][4];
#pragma unroll
    for (int nt = 0; nt < 16; nt++)
#pragma unroll
        for (int j = 0; j < 4; j++) acc[nt][j] = 0.f;

    const int rA0 = min(node0 + gid, NN - 1);
    const int rA1 = min(node0 + gid + 8, NN - 1);

    for (int kc = 0; kc < 16; kc++) {
        __syncthreads();
        for (int i = tid; i < 2 * 8 * 128; i += 256) {
            const int m   = i >> 10;
            const int rem = i & 1023;
            const int k   = rem >> 7;
            const int n   = rem & 127;
            const float* Wp = m ? Wr : Wl;
            Ws[m][k][n] = f2tf32(Wp[(size_t)(kc * 8 + k) * 128 + n]);
        }
        __syncthreads();

        const int c0 = kc * 8 + tig;
        const unsigned a0 = f2tf32(X[(size_t)rA0 * 128 + c0]);
        const unsigned a1 = f2tf32(X[(size_t)rA1 * 128 + c0]);
        const unsigned a2 = f2tf32(X[(size_t)rA0 * 128 + c0 + 4]);
        const unsigned a3 = f2tf32(X[(size_t)rA1 * 128 + c0 + 4]);

#pragma unroll
        for (int nt = 0; nt < 16; nt++) {
            const unsigned b0 = Ws[mat][tig][nt * 8 + gid];
            const unsigned b1 = Ws[mat][tig + 4][nt * 8 + gid];
            asm volatile(
                "mma.sync.aligned.m16n8k8.row.col.f32.tf32.tf32.f32 "
                "{%0,%1,%2,%3}, {%4,%5,%6,%7}, {%8,%9}, {%0,%1,%2,%3};"
                : "+f"(acc[nt][0]), "+f"(acc[nt][1]),
                  "+f"(acc[nt][2]), "+f"(acc[nt][3])
                : "r"(a0), "r"(a1), "r"(a2), "r"(a3), "r"(b0), "r"(b1));
        }
    }

    const float* Bp = mat ? Br : Bl;
    float* Yp = mat ? Yr : Yl;
    const int row0 = node0 + gid;
    const int row1 = row0 + 8;
#pragma unroll
    for (int nt = 0; nt < 16; nt++) {
        const int col = nt * 8 + tig * 2;
        const float b0v = Bp[col], b1v = Bp[col + 1];
        if (row0 < NN) {
            Yp[(size_t)row0 * 128 + col]     = acc[nt][0] + b0v;
            Yp[(size_t)row0 * 128 + col + 1] = acc[nt][1] + b1v;
        }
        if (row1 < NN) {
            Yp[(size_t)row1 * 128 + col]     = acc[nt][2] + b0v;
            Yp[(size_t)row1 * 128 + col + 1] = acc[nt][3] + b1v;
        }
    }
}

// ---------------- dual linear (fp32): Yl = X@Wl+Bl, Yr = X@Wr+Br ------------
template<int IN, int OUT>
__global__ __launch_bounds__(256)
void linear_dual_kernel(const float* __restrict__ X,
                        const float* __restrict__ Wl, const float* __restrict__ Bl,
                        const float* __restrict__ Wr, const float* __restrict__ Br,
                        float* __restrict__ Yl, float* __restrict__ Yr) {
    constexpr int TO  = OUT / 8;
    constexpr int NGR = 256 / TO;
    constexpr int NPB = NGR * 4;
    constexpr int KT  = (IN < 32) ? IN : 32;

    __shared__ float Xs[KT][NPB + 4];
    __shared__ float Wsl[KT][OUT];
    __shared__ float Wsr[KT][OUT];

    const int tid = threadIdx.x;
    const int og  = tid % TO;
    const int ng  = tid / TO;
    const int nb  = blockIdx.x * NPB;

    float accl[4][8], accr[4][8];
#pragma unroll
    for (int i = 0; i < 4; i++)
#pragma unroll
        for (int j = 0; j < 8; j++) { accl[i][j] = 0.f; accr[i][j] = 0.f; }

    for (int kt = 0; kt < IN; kt += KT) {
        __syncthreads();
        for (int idx = tid; idx < KT * OUT / 4; idx += 256) {
            const int k = idx / (OUT / 4), o4 = idx % (OUT / 4);
            ((float4*)Wsl[k])[o4] = ((const float4*)(Wl + (size_t)(kt + k) * OUT))[o4];
            ((float4*)Wsr[k])[o4] = ((const float4*)(Wr + (size_t)(kt + k) * OUT))[o4];
        }
        for (int idx = tid; idx < NPB * (KT / 4); idx += 256) {
            const int ni = idx / (KT / 4), f4 = idx % (KT / 4);
            const int gn = nb + ni;
            float4 xv = make_float4(0.f, 0.f, 0.f, 0.f);
            if (gn < NN)
                xv = ((const float4*)(X + (size_t)gn * IN + kt))[f4];
            Xs[f4 * 4 + 0][ni] = xv.x;
            Xs[f4 * 4 + 1][ni] = xv.y;
            Xs[f4 * 4 + 2][ni] = xv.z;
            Xs[f4 * 4 + 3][ni] = xv.w;
        }
        __syncthreads();
#pragma unroll
        for (int k = 0; k < KT; k++) {
            float xv[4];
#pragma unroll
            for (int i = 0; i < 4; i++) xv[i] = Xs[k][ng * 4 + i];
            const float4 wl0 = ((const float4*)&Wsl[k][og * 8])[0];
            const float4 wl1 = ((const float4*)&Wsl[k][og * 8])[1];
            const float4 wr0 = ((const float4*)&Wsr[k][og * 8])[0];
            const float4 wr1 = ((const float4*)&Wsr[k][og * 8])[1];
#pragma unroll
            for (int i = 0; i < 4; i++) {
                accl[i][0] += xv[i] * wl0.x; accl[i][1] += xv[i] * wl0.y;
                accl[i][2] += xv[i] * wl0.z; accl[i][3] += xv[i] * wl0.w;
                accl[i][4] += xv[i] * wl1.x; accl[i][5] += xv[i] * wl1.y;
                accl[i][6] += xv[i] * wl1.z; accl[i][7] += xv[i] * wl1.w;
                accr[i][0] += xv[i] * wr0.x; accr[i][1] += xv[i] * wr0.y;
                accr[i][2] += xv[i] * wr0.z; accr[i][3] += xv[i] * wr0.w;
                accr[i][4] += xv[i] * wr1.x; accr[i][5] += xv[i] * wr1.y;
                accr[i][6] += xv[i] * wr1.z; accr[i][7] += xv[i] * wr1.w;
            }
        }
    }

    const float4 bl0 = ((const float4*)(Bl + og * 8))[0];
    const float4 bl1 = ((const float4*)(Bl + og * 8))[1];
    const float4 br0 = ((const float4*)(Br + og * 8))[0];
    const float4 br1 = ((const float4*)(Br + og * 8))[1];
#pragma unroll
    for (int i = 0; i < 4; i++) {
        const int node = nb + ng * 4 + i;
        if (node >= NN) continue;
        float4 o;
        o = make_float4(accl[i][0]+bl0.x, accl[i][1]+bl0.y, accl[i][2]+bl0.z, accl[i][3]+bl0.w);
        ((float4*)(Yl + (size_t)node * OUT + og * 8))[0] = o;
        o = make_float4(accl[i][4]+bl1.x, accl[i][5]+bl1.y, accl[i][6]+bl1.z, accl[i][7]+bl1.w);
        ((float4*)(Yl + (size_t)node * OUT + og * 8))[1] = o;
        o = make_float4(accr[i][0]+br0.x, accr[i][1]+br0.y, accr[i][2]+br0.z, accr[i][3]+br0.w);
        ((float4*)(Yr + (size_t)node * OUT + og * 8))[0] = o;
        o = make_float4(accr[i][4]+br1.x, accr[i][5]+br1.y, accr[i][6]+br1.z, accr[i][7]+br1.w);
        ((float4*)(Yr + (size_t)node * OUT + og * 8))[1] = o;
    }
}

// ---------------- fused GATv2 edge pass (CT=128, H=2), warp/dst, ILP4 -------
__global__ void gat_fused128_kernel(const float* __restrict__ att,
                                    const float* __restrict__ B,
                                    float* __restrict__ out) {
    const int node = (blockIdx.x * blockDim.x + threadIdx.x) >> 5;
    if (node >= NN) return;
    const int lane = threadIdx.x & 31;

    const float4 xrv  = *(const float4*)(g_xr + (size_t)node * 128 + lane * 4);
    const float4 attv = *(const float4*)(att + lane * 4);

    float s_self;
    {
        const float4 xlv = *(const float4*)(g_xl + (size_t)node * 128 + lane * 4);
        float t, sc = 0.f;
        t = xlv.x + xrv.x; t = t > 0.f ? t : 0.2f * t; sc += t * attv.x;
        t = xlv.y + xrv.y; t = t > 0.f ? t : 0.2f * t; sc += t * attv.y;
        t = xlv.z + xrv.z; t = t > 0.f ? t : 0.2f * t; sc += t * attv.z;
        t = xlv.w + xrv.w; t = t > 0.f ? t : 0.2f * t; sc += t * attv.w;
#pragma unroll
        for (int off = 1; off <= 8; off <<= 1)
            sc += __shfl_xor_sync(0xffffffffu, sc, off);
        s_self = sc;
    }

    int p  = g_rowptr[node];
    const int pe = g_rowptr[node + 1];

    float  dd[4] = {0.f, 0.f, 0.f, 0.f};
    float4 A[4];
#pragma unroll
    for (int j = 0; j < 4; j++) A[j] = make_float4(0.f, 0.f, 0.f, 0.f);

    for (; p + 3 < pe; p += 4) {
        int s[4];
#pragma unroll
        for (int j = 0; j < 4; j++) s[j] = g_csrc[p + j];
        float4 a[4];
#pragma unroll
        for (int j = 0; j < 4; j++)
            a[j] = *(const float4*)(g_xl + (size_t)s[j] * 128 + lane * 4);

        float pp[4];
#pragma unroll
        for (int j = 0; j < 4; j++) {
            float t, sc = 0.f;
            t = a[j].x + xrv.x; t = t > 0.f ? t : 0.2f * t; sc += t * attv.x;
            t = a[j].y + xrv.y; t = t > 0.f ? t : 0.2f * t; sc += t * attv.y;
            t = a[j].z + xrv.z; t = t > 0.f ? t : 0.2f * t; sc += t * attv.z;
            t = a[j].w + xrv.w; t = t > 0.f ? t : 0.2f * t; sc += t * attv.w;
            pp[j] = sc;
        }
#pragma unroll
        for (int off = 1; off <= 8; off <<= 1)
#pragma unroll
            for (int j = 0; j < 4; j++)
                pp[j] += __shfl_xor_sync(0xffffffffu, pp[j], off);
#pragma unroll
        for (int j = 0; j < 4; j++) {
            const float w = __expf(pp[j] - s_self);
            dd[j] += w;
            A[j].x += w * a[j].x;
            A[j].y += w * a[j].y;
            A[j].z += w * a[j].z;
            A[j].w += w * a[j].w;
        }
    }
    for (; p < pe; ++p) {
        const int s0 = g_csrc[p];
        const float4 a0 = *(const float4*)(g_xl + (size_t)s0 * 128 + lane * 4);
        float t, p0 = 0.f;
        t = a0.x + xrv.x; t = t > 0.f ? t : 0.2f * t; p0 += t * attv.x;
        t = a0.y + xrv.y; t = t > 0.f ? t : 0.2f * t; p0 += t * attv.y;
        t = a0.z + xrv.z; t = t > 0.f ? t : 0.2f * t; p0 += t * attv.z;
        t = a0.w + xrv.w; t = t > 0.f ? t : 0.2f * t; p0 += t * attv.w;
#pragma unroll
        for (int off = 1; off <= 8; off <<= 1)
            p0 += __shfl_xor_sync(0xffffffffu, p0, off);
        const float w = __expf(p0 - s_self);
        dd[0] += w;
        A[0].x += w * a0.x;
        A[0].y += w * a0.y;
        A[0].z += w * a0.z;
        A[0].w += w * a0.w;
    }

    const float d = dd[0] + dd[1] + dd[2] + dd[3];
    float4 acc;
    acc.x = A[0].x + A[1].x + A[2].x + A[3].x;
    acc.y = A[0].y + A[1].y + A[2].y + A[3].y;
    acc.z = A[0].z + A[1].z + A[2].z + A[3].z;
    acc.w = A[0].w + A[1].w + A[2].w + A[3].w;

    const float inv = 1.f / d;
    const float4 bv = *(const float4*)(B + lane * 4);
    float4 o;
    o.x = acc.x * inv + bv.x; o.x = o.x > 0.f ? o.x : expm1f(o.x);
    o.y = acc.y * inv + bv.y; o.y = o.y > 0.f ? o.y : expm1f(o.y);
    o.z = acc.z * inv + bv.z; o.z = o.z > 0.f ? o.z : expm1f(o.z);
    o.w = acc.w * inv + bv.w; o.w = o.w > 0.f ? o.w : expm1f(o.w);
    *(float4*)(out + (size_t)node * 128 + lane * 4) = o;
}

// ---------------- fused GATv2 edge pass (CT=32, H=1), warp/dst, ILP4 --------
__global__ void gat_fused32_kernel(const float* __restrict__ att,
                                   const float* __restrict__ B,
                                   float* __restrict__ out) {
    const int node = (blockIdx.x * blockDim.x + threadIdx.x) >> 5;
    if (node >= NN) return;
    const int lane = threadIdx.x & 31;

    const float xrv  = g_xr[(size_t)node * 32 + lane];
    const float attv = att[lane];

    float s_self;
    {
        const float xlv = g_xl[(size_t)node * 32 + lane];
        float t = xlv + xrv; t = t > 0.f ? t : 0.2f * t;
        float sc = t * attv;
#pragma unroll
        for (int off = 1; off <= 16; off <<= 1)
            sc += __shfl_xor_sync(0xffffffffu, sc, off);
        s_self = sc;
    }

    int p  = g_rowptr[node];
    const int pe = g_rowptr[node + 1];

    float dd[4] = {0.f, 0.f, 0.f, 0.f};
    float A[4] = {0.f, 0.f, 0.f, 0.f};

    for (; p + 3 < pe; p += 4) {
        float a[4], pp[4];
#pragma unroll
        for (int j = 0; j < 4; j++) {
            const int s = g_csrc[p + j];
            a[j] = g_xl[(size_t)s * 32 + lane];
            float t = a[j] + xrv; t = t > 0.f ? t : 0.2f * t;
            pp[j] = t * attv;
        }
#pragma unroll
        for (int off = 1; off <= 16; off <<= 1)
#pragma unroll
            for (int j = 0; j < 4; j++)
                pp[j] += __shfl_xor_sync(0xffffffffu, pp[j], off);
#pragma unroll
        for (int j = 0; j < 4; j++) {
            const float w = __expf(pp[j] - s_self);
            dd[j] += w; A[j] += w * a[j];
        }
    }
    for (; p < pe; ++p) {
        const int s = g_csrc[p];
        const float a0 = g_xl[(size_t)s * 32 + lane];
        float t = a0 + xrv; t = t > 0.f ? t : 0.2f * t;
        float p0 = t * attv;
#pragma unroll
        for (int off = 1; off <= 16; off <<= 1)
            p0 += __shfl_xor_sync(0xffffffffu, p0, off);
        const float w = __expf(p0 - s_self);
        dd[0] += w; A[0] += w * a0;
    }

    const float d = dd[0] + dd[1] + dd[2] + dd[3];
    const float acc = A[0] + A[1] + A[2] + A[3];

    float o = acc / d + B[lane];
    o = o > 0.f ? o : expm1f(o);
    out[(size_t)node * 32 + lane] = o;
}

// ---------------- pooling ----------------------------------------------------
__global__ void pool_init_kernel() {
    int i = blockIdx.x * blockDim.x + threadIdx.x;
    if (i < NG * 32) { g_psum[i] = 0.f; g_pmax[i] = -INFINITY; }
    if (i < NG) g_cntf[i] = 0.f;
}

__global__ __launch_bounds__(256)
void pool_accum_kernel(const float* __restrict__ h,
                       const int* __restrict__ batch) {
    __shared__ float ssum[NG * 32];
    __shared__ float smax[NG * 32];
    __shared__ int   scnt[NG];
    const int tid = threadIdx.x;
    for (int i = tid; i < NG * 32; i += 256) { ssum[i] = 0.f; smax[i] = -INFINITY; }
    if (tid < NG) scnt[tid] = 0;
    __syncthreads();

    const int warp = tid >> 5, lane = tid & 31;
    const int nbase = blockIdx.x * 256 + warp * 32;
#pragma unroll 4
    for (int i = 0; i < 32; i++) {
        const int node = nbase + i;
        if (node >= NN) break;
        const int g = batch[node];
        const float v = h[(size_t)node * 32 + lane];
        atomicAdd(&ssum[g * 32 + lane], v);
        atomicMaxF(&smax[g * 32 + lane], v);
        if (lane == 0) atomicAdd(&scnt[g], 1);
    }
    __syncthreads();

    for (int i = tid; i < NG * 32; i += 256) {
        if (ssum[i] != 0.f) atomicAdd(&g_psum[i], ssum[i]);
        if (smax[i] != -INFINITY) atomicMaxF(&g_pmax[i], smax[i]);
    }
    if (tid < NG && scnt[tid] > 0) atomicAdd(&g_cntf[tid], (float)scnt[tid]);
}

__global__ void pool_final_kernel(float* __restrict__ out) {
    const int i = blockIdx.x * blockDim.x + threadIdx.x;
    if (i >= NG * 64) return;
    const int g = i / 64, c = i % 64;
    out[i] = (c < 32) ? g_psum[g * 32 + c] / g_cntf[g]
                      : g_pmax[g * 32 + (c - 32)];
}

// ---------------- launch ------------------------------------------------------
static inline int gridFor(long long n) { return (int)((n + TB - 1) / TB); }

extern "C" void kernel_launch(void* const* d_in, const int* in_sizes, int n_in,
                              void* d_out, int out_size) {
    const float* x     = (const float*)d_in[0];
    const int*   ei    = (const int*)d_in[1];
    const int*   batch = (const int*)d_in[2];
    const float *Wl1=(const float*)d_in[3],  *bl1=(const float*)d_in[4];
    const float *Wr1=(const float*)d_in[5],  *br1=(const float*)d_in[6];
    const float *att1=(const float*)d_in[7], *b1=(const float*)d_in[8];
    const float *Wl2=(const float*)d_in[9],  *bl2=(const float*)d_in[10];
    const float *Wr2=(const float*)d_in[11], *br2=(const float*)d_in[12];
    const float *att2=(const float*)d_in[13],*b2=(const float*)d_in[14];
    const float *Wl3=(const float*)d_in[15], *bl3=(const float*)d_in[16];
    const float *Wr3=(const float*)d_in[17], *br3=(const float*)d_in[18];
    const float *att3=(const float*)d_in[19],*b3=(const float*)d_in[20];

    float *p_xl, *p_xr, *p_h;
    cudaGetSymbolAddress((void**)&p_xl, g_xl);
    cudaGetSymbolAddress((void**)&p_xr, g_xr);
    cudaGetSymbolAddress((void**)&p_h,  g_h);

    static cudaStream_t s2 = nullptr;
    static cudaEvent_t evFork = nullptr, evJoin = nullptr;
    if (s2 == nullptr) {
        cudaStreamCreateWithFlags(&s2, cudaStreamNonBlocking);
        cudaEventCreateWithFlags(&evFork, cudaEventDisableTiming);
        cudaEventCreateWithFlags(&evJoin, cudaEventDisableTiming);
    }

    const int gNodeWarp = gridFor((long long)NN * 32);
    const int gLin128   = (NN + 63) / 64;
    const int gLinTf    = (NN + 63) / 64;
    const int gLin32    = (NN + 255) / 256;
    const int gPool     = (NN + 255) / 256;

    // ---- fork: layer-1 linear + pool_init on s2, concurrent with CSR build
    cudaEventRecord(evFork, 0);
    cudaStreamWaitEvent(s2, evFork, 0);
    linear_dual_kernel<8, 128><<<gLin128, 256, 0, s2>>>(x, Wl1, bl1, Wr1, br1,
                                                        p_xl, p_xr);
    pool_init_kernel<<<gridFor(NG * 32), TB, 0, s2>>>();
    cudaEventRecord(evJoin, s2);

    // ---- CSR (dst-indexed) build on default stream -------------------------
    deg_count_kernel<<<gridFor(NE), TB>>>(ei);
    scan_kernel<<<1, 1024>>>();
    fill_kernel<<<gridFor(ET), TB>>>(ei);

    cudaStreamWaitEvent(0, evJoin, 0);

    // ---- layer 1: 8 -> 128 (H=2, C=64)
    gat_fused128_kernel<<<gNodeWarp, TB>>>(att1, b1, p_h);

    // ---- layer 2: 128 -> 128 (H=2, C=64), TF32 tensor GEMM
    linear_tf32_dual_kernel<<<gLinTf, 256>>>(p_h, Wl2, bl2, Wr2, br2, p_xl, p_xr);
    gat_fused128_kernel<<<gNodeWarp, TB>>>(att2, b2, p_h);

    // ---- layer 3: 128 -> 32 (H=1, C=32)
    linear_dual_kernel<128, 32><<<gLin32, 256>>>(p_h, Wl3, bl3, Wr3, br3, p_xl, p_xr);
    gat_fused32_kernel<<<gNodeWarp, TB>>>(att3, b3, p_h);

    // ---- pooling
    pool_accum_kernel<<<gPool, 256>>>(p_h, batch);
    pool_final_kernel<<<gridFor(NG * 64), TB>>>((float*)d_out);
}

// round 15
// speedup vs baseline: 1.5281x; 1.2037x over previous
#include <cuda_runtime.h>
#include <math.h>

// GATv2 x3 + pooling: multi-block CSR scan + offset-softmax fused edge pass
// (ILP4), TF32 mma.sync dual linear for 128->128, stream-forked layer-1
// linear + pool_init overlapped with CSR build, SMEM pooling.
namespace {
constexpr int NN = 50000;
constexpr int NE = 800000;
constexpr int ET = NE + NN;
constexpr int NG = 16;
constexpr int TB = 256;
constexpr int NSCAN = (NN + 255) / 256;   // 196 scan blocks
}

// ---------------- scratch ---------------------------------------------------
__device__ __align__(16) float g_xl[(size_t)NN * 128];
__device__ __align__(16) float g_xr[(size_t)NN * 128];
__device__ __align__(16) float g_h[(size_t)NN * 128];
__device__ int g_deg[NN];            // zero at load; re-zeroed in fill
__device__ int g_rowptr[NN + 1];
__device__ int g_cur[NN];
__device__ int g_csrc[ET];
__device__ int g_bsum[256];
__device__ int g_boff[256];
__device__ float g_psum[NG * 32];
__device__ float g_pmax[NG * 32];
__device__ float g_cntf[NG];

__device__ __forceinline__ void atomicMaxF(float* a, float v) {
    if (v >= 0.f) atomicMax((int*)a, __float_as_int(v));
    else          atomicMin((unsigned int*)a, __float_as_uint(v));
}

__device__ __forceinline__ unsigned f2tf32(float x) {
    unsigned u;
    asm("cvt.rna.tf32.f32 %0, %1;" : "=r"(u) : "f"(x));
    return u;
}

// ---------------- CSR build -------------------------------------------------
__global__ void deg_count_kernel(const int* __restrict__ ei) {
    int e = blockIdx.x * blockDim.x + threadIdx.x;
    if (e < NE) atomicAdd(&g_deg[ei[NE + e]], 1);
}

// phase A: per-block sums of (deg+1)
__global__ void scanA_kernel() {
    __shared__ int sh[256];
    const int tid = threadIdx.x;
    const int node = blockIdx.x * 256 + tid;
    sh[tid] = (node < NN) ? g_deg[node] + 1 : 0;
    __syncthreads();
#pragma unroll
    for (int off = 128; off > 0; off >>= 1) {
        if (tid < off) sh[tid] += sh[tid + off];
        __syncthreads();
    }
    if (tid == 0) g_bsum[blockIdx.x] = sh[0];
}

// phase B: exclusive scan over block sums (single block)
__global__ void scanB_kernel() {
    __shared__ int sh[256];
    const int tid = threadIdx.x;
    sh[tid] = (tid < NSCAN) ? g_bsum[tid] : 0;
    __syncthreads();
#pragma unroll
    for (int off = 1; off < 256; off <<= 1) {
        int add = (tid >= off) ? sh[tid - off] : 0;
        __syncthreads();
        sh[tid] += add;
        __syncthreads();
    }
    g_boff[tid] = (tid == 0) ? 0 : sh[tid - 1];
    if (tid == 0) g_rowptr[NN] = ET;
}

// phase C: per-block exclusive scan + offset -> rowptr/cur
__global__ void scanC_kernel() {
    __shared__ int sh[256];
    const int tid = threadIdx.x;
    const int node = blockIdx.x * 256 + tid;
    const int val = (node < NN) ? g_deg[node] + 1 : 0;
    sh[tid] = val;
    __syncthreads();
#pragma unroll
    for (int off = 1; off < 256; off <<= 1) {
        int add = (tid >= off) ? sh[tid - off] : 0;
        __syncthreads();
        sh[tid] += add;
        __syncthreads();
    }
    if (node < NN) {
        const int pos = g_boff[blockIdx.x] + sh[tid] - val;   // exclusive
        g_rowptr[node] = pos;
        g_cur[node] = pos;
    }
}

__global__ void fill_kernel(const int* __restrict__ ei) {
    int e = blockIdx.x * blockDim.x + threadIdx.x;
    if (e < NN) g_deg[e] = 0;        // re-zero for next replay
    if (e >= ET) return;
    int src, dst;
    if (e < NE) { src = ei[e]; dst = ei[NE + e]; }
    else        { src = e - NE; dst = src; }
    int pos = atomicAdd(&g_cur[dst], 1);
    g_csrc[pos] = src;
}

// ---------------- TF32 mma dual linear: 128 -> 128 x 2 matrices -------------
__global__ __launch_bounds__(256)
void linear_tf32_dual_kernel(const float* __restrict__ X,
                             const float* __restrict__ Wl, const float* __restrict__ Bl,
                             const float* __restrict__ Wr, const float* __restrict__ Br,
                             float* __restrict__ Yl, float* __restrict__ Yr) {
    __shared__ unsigned Ws[2][8][136];
    const int tid  = threadIdx.x;
    const int warp = tid >> 5, lane = tid & 31;
    const int mat  = warp & 1;
    const int rt   = warp >> 1;
    const int node0 = blockIdx.x * 64 + rt * 16;
    const int gid = lane >> 2;
    const int tig = lane & 3;

    float acc[16][4];
#pragma unroll
    for (int nt = 0; nt < 16; nt++)
#pragma unroll
        for (int j = 0; j < 4; j++) acc[nt][j] = 0.f;

    const int rA0 = min(node0 + gid, NN - 1);
    const int rA1 = min(node0 + gid + 8, NN - 1);

    for (int kc = 0; kc < 16; kc++) {
        __syncthreads();
        for (int i = tid; i < 2 * 8 * 128; i += 256) {
            const int m   = i >> 10;
            const int rem = i & 1023;
            const int k   = rem >> 7;
            const int n   = rem & 127;
            const float* Wp = m ? Wr : Wl;
            Ws[m][k][n] = f2tf32(Wp[(size_t)(kc * 8 + k) * 128 + n]);
        }
        __syncthreads();

        const int c0 = kc * 8 + tig;
        const unsigned a0 = f2tf32(X[(size_t)rA0 * 128 + c0]);
        const unsigned a1 = f2tf32(X[(size_t)rA1 * 128 + c0]);
        const unsigned a2 = f2tf32(X[(size_t)rA0 * 128 + c0 + 4]);
        const unsigned a3 = f2tf32(X[(size_t)rA1 * 128 + c0 + 4]);

#pragma unroll
        for (int nt = 0; nt < 16; nt++) {
            const unsigned b0 = Ws[mat][tig][nt * 8 + gid];
            const unsigned b1 = Ws[mat][tig + 4][nt * 8 + gid];
            asm volatile(
                "mma.sync.aligned.m16n8k8.row.col.f32.tf32.tf32.f32 "
                "{%0,%1,%2,%3}, {%4,%5,%6,%7}, {%8,%9}, {%0,%1,%2,%3};"
                : "+f"(acc[nt][0]), "+f"(acc[nt][1]),
                  "+f"(acc[nt][2]), "+f"(acc[nt][3])
                : "r"(a0), "r"(a1), "r"(a2), "r"(a3), "r"(b0), "r"(b1));
        }
    }

    const float* Bp = mat ? Br : Bl;
    float* Yp = mat ? Yr : Yl;
    const int row0 = node0 + gid;
    const int row1 = row0 + 8;
#pragma unroll
    for (int nt = 0; nt < 16; nt++) {
        const int col = nt * 8 + tig * 2;
        const float b0v = Bp[col], b1v = Bp[col + 1];
        if (row0 < NN) {
            Yp[(size_t)row0 * 128 + col]     = acc[nt][0] + b0v;
            Yp[(size_t)row0 * 128 + col + 1] = acc[nt][1] + b1v;
        }
        if (row1 < NN) {
            Yp[(size_t)row1 * 128 + col]     = acc[nt][2] + b0v;
            Yp[(size_t)row1 * 128 + col + 1] = acc[nt][3] + b1v;
        }
    }
}

// ---------------- dual linear (fp32): Yl = X@Wl+Bl, Yr = X@Wr+Br ------------
template<int IN, int OUT>
__global__ __launch_bounds__(256)
void linear_dual_kernel(const float* __restrict__ X,
                        const float* __restrict__ Wl, const float* __restrict__ Bl,
                        const float* __restrict__ Wr, const float* __restrict__ Br,
                        float* __restrict__ Yl, float* __restrict__ Yr) {
    constexpr int TO  = OUT / 8;
    constexpr int NGR = 256 / TO;
    constexpr int NPB = NGR * 4;
    constexpr int KT  = (IN < 32) ? IN : 32;

    __shared__ float Xs[KT][NPB + 4];
    __shared__ float Wsl[KT][OUT];
    __shared__ float Wsr[KT][OUT];

    const int tid = threadIdx.x;
    const int og  = tid % TO;
    const int ng  = tid / TO;
    const int nb  = blockIdx.x * NPB;

    float accl[4][8], accr[4][8];
#pragma unroll
    for (int i = 0; i < 4; i++)
#pragma unroll
        for (int j = 0; j < 8; j++) { accl[i][j] = 0.f; accr[i][j] = 0.f; }

    for (int kt = 0; kt < IN; kt += KT) {
        __syncthreads();
        for (int idx = tid; idx < KT * OUT / 4; idx += 256) {
            const int k = idx / (OUT / 4), o4 = idx % (OUT / 4);
            ((float4*)Wsl[k])[o4] = ((const float4*)(Wl + (size_t)(kt + k) * OUT))[o4];
            ((float4*)Wsr[k])[o4] = ((const float4*)(Wr + (size_t)(kt + k) * OUT))[o4];
        }
        for (int idx = tid; idx < NPB * (KT / 4); idx += 256) {
            const int ni = idx / (KT / 4), f4 = idx % (KT / 4);
            const int gn = nb + ni;
            float4 xv = make_float4(0.f, 0.f, 0.f, 0.f);
            if (gn < NN)
                xv = ((const float4*)(X + (size_t)gn * IN + kt))[f4];
            Xs[f4 * 4 + 0][ni] = xv.x;
            Xs[f4 * 4 + 1][ni] = xv.y;
            Xs[f4 * 4 + 2][ni] = xv.z;
            Xs[f4 * 4 + 3][ni] = xv.w;
        }
        __syncthreads();
#pragma unroll
        for (int k = 0; k < KT; k++) {
            float xv[4];
#pragma unroll
            for (int i = 0; i < 4; i++) xv[i] = Xs[k][ng * 4 + i];
            const float4 wl0 = ((const float4*)&Wsl[k][og * 8])[0];
            const float4 wl1 = ((const float4*)&Wsl[k][og * 8])[1];
            const float4 wr0 = ((const float4*)&Wsr[k][og * 8])[0];
            const float4 wr1 = ((const float4*)&Wsr[k][og * 8])[1];
#pragma unroll
            for (int i = 0; i < 4; i++) {
                accl[i][0] += xv[i] * wl0.x; accl[i][1] += xv[i] * wl0.y;
                accl[i][2] += xv[i] * wl0.z; accl[i][3] += xv[i] * wl0.w;
                accl[i][4] += xv[i] * wl1.x; accl[i][5] += xv[i] * wl1.y;
                accl[i][6] += xv[i] * wl1.z; accl[i][7] += xv[i] * wl1.w;
                accr[i][0] += xv[i] * wr0.x; accr[i][1] += xv[i] * wr0.y;
                accr[i][2] += xv[i] * wr0.z; accr[i][3] += xv[i] * wr0.w;
                accr[i][4] += xv[i] * wr1.x; accr[i][5] += xv[i] * wr1.y;
                accr[i][6] += xv[i] * wr1.z; accr[i][7] += xv[i] * wr1.w;
            }
        }
    }

    const float4 bl0 = ((const float4*)(Bl + og * 8))[0];
    const float4 bl1 = ((const float4*)(Bl + og * 8))[1];
    const float4 br0 = ((const float4*)(Br + og * 8))[0];
    const float4 br1 = ((const float4*)(Br + og * 8))[1];
#pragma unroll
    for (int i = 0; i < 4; i++) {
        const int node = nb + ng * 4 + i;
        if (node >= NN) continue;
        float4 o;
        o = make_float4(accl[i][0]+bl0.x, accl[i][1]+bl0.y, accl[i][2]+bl0.z, accl[i][3]+bl0.w);
        ((float4*)(Yl + (size_t)node * OUT + og * 8))[0] = o;
        o = make_float4(accl[i][4]+bl1.x, accl[i][5]+bl1.y, accl[i][6]+bl1.z, accl[i][7]+bl1.w);
        ((float4*)(Yl + (size_t)node * OUT + og * 8))[1] = o;
        o = make_float4(accr[i][0]+br0.x, accr[i][1]+br0.y, accr[i][2]+br0.z, accr[i][3]+br0.w);
        ((float4*)(Yr + (size_t)node * OUT + og * 8))[0] = o;
        o = make_float4(accr[i][4]+br1.x, accr[i][5]+br1.y, accr[i][6]+br1.z, accr[i][7]+br1.w);
        ((float4*)(Yr + (size_t)node * OUT + og * 8))[1] = o;
    }
}

// ---------------- fused GATv2 edge pass (CT=128, H=2), warp/dst, ILP4 -------
__global__ void gat_fused128_kernel(const float* __restrict__ att,
                                    const float* __restrict__ B,
                                    float* __restrict__ out) {
    const int node = (blockIdx.x * blockDim.x + threadIdx.x) >> 5;
    if (node >= NN) return;
    const int lane = threadIdx.x & 31;

    const float4 xrv  = *(const float4*)(g_xr + (size_t)node * 128 + lane * 4);
    const float4 attv = *(const float4*)(att + lane * 4);

    float s_self;
    {
        const float4 xlv = *(const float4*)(g_xl + (size_t)node * 128 + lane * 4);
        float t, sc = 0.f;
        t = xlv.x + xrv.x; t = t > 0.f ? t : 0.2f * t; sc += t * attv.x;
        t = xlv.y + xrv.y; t = t > 0.f ? t : 0.2f * t; sc += t * attv.y;
        t = xlv.z + xrv.z; t = t > 0.f ? t : 0.2f * t; sc += t * attv.z;
        t = xlv.w + xrv.w; t = t > 0.f ? t : 0.2f * t; sc += t * attv.w;
#pragma unroll
        for (int off = 1; off <= 8; off <<= 1)
            sc += __shfl_xor_sync(0xffffffffu, sc, off);
        s_self = sc;
    }

    int p  = g_rowptr[node];
    const int pe = g_rowptr[node + 1];

    float  dd[4] = {0.f, 0.f, 0.f, 0.f};
    float4 A[4];
#pragma unroll
    for (int j = 0; j < 4; j++) A[j] = make_float4(0.f, 0.f, 0.f, 0.f);

    for (; p + 3 < pe; p += 4) {
        int s[4];
#pragma unroll
        for (int j = 0; j < 4; j++) s[j] = g_csrc[p + j];
        float4 a[4];
#pragma unroll
        for (int j = 0; j < 4; j++)
            a[j] = *(const float4*)(g_xl + (size_t)s[j] * 128 + lane * 4);

        float pp[4];
#pragma unroll
        for (int j = 0; j < 4; j++) {
            float t, sc = 0.f;
            t = a[j].x + xrv.x; t = t > 0.f ? t : 0.2f * t; sc += t * attv.x;
            t = a[j].y + xrv.y; t = t > 0.f ? t : 0.2f * t; sc += t * attv.y;
            t = a[j].z + xrv.z; t = t > 0.f ? t : 0.2f * t; sc += t * attv.z;
            t = a[j].w + xrv.w; t = t > 0.f ? t : 0.2f * t; sc += t * attv.w;
            pp[j] = sc;
        }
#pragma unroll
        for (int off = 1; off <= 8; off <<= 1)
#pragma unroll
            for (int j = 0; j < 4; j++)
                pp[j] += __shfl_xor_sync(0xffffffffu, pp[j], off);
#pragma unroll
        for (int j = 0; j < 4; j++) {
            const float w = __expf(pp[j] - s_self);
            dd[j] += w;
            A[j].x += w * a[j].x;
            A[j].y += w * a[j].y;
            A[j].z += w * a[j].z;
            A[j].w += w * a[j].w;
        }
    }
    for (; p < pe; ++p) {
        const int s0 = g_csrc[p];
        const float4 a0 = *(const float4*)(g_xl + (size_t)s0 * 128 + lane * 4);
        float t, p0 = 0.f;
        t = a0.x + xrv.x; t = t > 0.f ? t : 0.2f * t; p0 += t * attv.x;
        t = a0.y + xrv.y; t = t > 0.f ? t : 0.2f * t; p0 += t * attv.y;
        t = a0.z + xrv.z; t = t > 0.f ? t : 0.2f * t; p0 += t * attv.z;
        t = a0.w + xrv.w; t = t > 0.f ? t : 0.2f * t; p0 += t * attv.w;
#pragma unroll
        for (int off = 1; off <= 8; off <<= 1)
            p0 += __shfl_xor_sync(0xffffffffu, p0, off);
        const float w = __expf(p0 - s_self);
        dd[0] += w;
        A[0].x += w * a0.x;
        A[0].y += w * a0.y;
        A[0].z += w * a0.z;
        A[0].w += w * a0.w;
    }

    const float d = dd[0] + dd[1] + dd[2] + dd[3];
    float4 acc;
    acc.x = A[0].x + A[1].x + A[2].x + A[3].x;
    acc.y = A[0].y + A[1].y + A[2].y + A[3].y;
    acc.z = A[0].z + A[1].z + A[2].z + A[3].z;
    acc.w = A[0].w + A[1].w + A[2].w + A[3].w;

    const float inv = 1.f / d;
    const float4 bv = *(const float4*)(B + lane * 4);
    float4 o;
    o.x = acc.x * inv + bv.x; o.x = o.x > 0.f ? o.x : expm1f(o.x);
    o.y = acc.y * inv + bv.y; o.y = o.y > 0.f ? o.y : expm1f(o.y);
    o.z = acc.z * inv + bv.z; o.z = o.z > 0.f ? o.z : expm1f(o.z);
    o.w = acc.w * inv + bv.w; o.w = o.w > 0.f ? o.w : expm1f(o.w);
    *(float4*)(out + (size_t)node * 128 + lane * 4) = o;
}

// ---------------- fused GATv2 edge pass (CT=32, H=1), warp/dst, ILP4 --------
__global__ void gat_fused32_kernel(const float* __restrict__ att,
                                   const float* __restrict__ B,
                                   float* __restrict__ out) {
    const int node = (blockIdx.x * blockDim.x + threadIdx.x) >> 5;
    if (node >= NN) return;
    const int lane = threadIdx.x & 31;

    const float xrv  = g_xr[(size_t)node * 32 + lane];
    const float attv = att[lane];

    float s_self;
    {
        const float xlv = g_xl[(size_t)node * 32 + lane];
        float t = xlv + xrv; t = t > 0.f ? t : 0.2f * t;
        float sc = t * attv;
#pragma unroll
        for (int off = 1; off <= 16; off <<= 1)
            sc += __shfl_xor_sync(0xffffffffu, sc, off);
        s_self = sc;
    }

    int p  = g_rowptr[node];
    const int pe = g_rowptr[node + 1];

    float dd[4] = {0.f, 0.f, 0.f, 0.f};
    float A[4] = {0.f, 0.f, 0.f, 0.f};

    for (; p + 3 < pe; p += 4) {
        float a[4], pp[4];
#pragma unroll
        for (int j = 0; j < 4; j++) {
            const int s = g_csrc[p + j];
            a[j] = g_xl[(size_t)s * 32 + lane];
            float t = a[j] + xrv; t = t > 0.f ? t : 0.2f * t;
            pp[j] = t * attv;
        }
#pragma unroll
        for (int off = 1; off <= 16; off <<= 1)
#pragma unroll
            for (int j = 0; j < 4; j++)
                pp[j] += __shfl_xor_sync(0xffffffffu, pp[j], off);
#pragma unroll
        for (int j = 0; j < 4; j++) {
            const float w = __expf(pp[j] - s_self);
            dd[j] += w; A[j] += w * a[j];
        }
    }
    for (; p < pe; ++p) {
        const int s = g_csrc[p];
        const float a0 = g_xl[(size_t)s * 32 + lane];
        float t = a0 + xrv; t = t > 0.f ? t : 0.2f * t;
        float p0 = t * attv;
#pragma unroll
        for (int off = 1; off <= 16; off <<= 1)
            p0 += __shfl_xor_sync(0xffffffffu, p0, off);
        const float w = __expf(p0 - s_self);
        dd[0] += w; A[0] += w * a0;
    }

    const float d = dd[0] + dd[1] + dd[2] + dd[3];
    const float acc = A[0] + A[1] + A[2] + A[3];

    float o = acc / d + B[lane];
    o = o > 0.f ? o : expm1f(o);
    out[(size_t)node * 32 + lane] = o;
}

// ---------------- pooling ----------------------------------------------------
__global__ void pool_init_kernel() {
    int i = blockIdx.x * blockDim.x + threadIdx.x;
    if (i < NG * 32) { g_psum[i] = 0.f; g_pmax[i] = -INFINITY; }
    if (i < NG) g_cntf[i] = 0.f;
}

__global__ __launch_bounds__(256)
void pool_accum_kernel(const float* __restrict__ h,
                       const int* __restrict__ batch) {
    __shared__ float ssum[NG * 32];
    __shared__ float smax[NG * 32];
    __shared__ int   scnt[NG];
    const int tid = threadIdx.x;
    for (int i = tid; i < NG * 32; i += 256) { ssum[i] = 0.f; smax[i] = -INFINITY; }
    if (tid < NG) scnt[tid] = 0;
    __syncthreads();

    const int warp = tid >> 5, lane = tid & 31;
    const int nbase = blockIdx.x * 256 + warp * 32;
#pragma unroll 4
    for (int i = 0; i < 32; i++) {
        const int node = nbase + i;
        if (node >= NN) break;
        const int g = batch[node];
        const float v = h[(size_t)node * 32 + lane];
        atomicAdd(&ssum[g * 32 + lane], v);
        atomicMaxF(&smax[g * 32 + lane], v);
        if (lane == 0) atomicAdd(&scnt[g], 1);
    }
    __syncthreads();

    for (int i = tid; i < NG * 32; i += 256) {
        if (ssum[i] != 0.f) atomicAdd(&g_psum[i], ssum[i]);
        if (smax[i] != -INFINITY) atomicMaxF(&g_pmax[i], smax[i]);
    }
    if (tid < NG && scnt[tid] > 0) atomicAdd(&g_cntf[tid], (float)scnt[tid]);
}

__global__ void pool_final_kernel(float* __restrict__ out) {
    const int i = blockIdx.x * blockDim.x + threadIdx.x;
    if (i >= NG * 64) return;
    const int g = i / 64, c = i % 64;
    out[i] = (c < 32) ? g_psum[g * 32 + c] / g_cntf[g]
                      : g_pmax[g * 32 + (c - 32)];
}

// ---------------- launch ------------------------------------------------------
static inline int gridFor(long long n) { return (int)((n + TB - 1) / TB); }

extern "C" void kernel_launch(void* const* d_in, const int* in_sizes, int n_in,
                              void* d_out, int out_size) {
    const float* x     = (const float*)d_in[0];
    const int*   ei    = (const int*)d_in[1];
    const int*   batch = (const int*)d_in[2];
    const float *Wl1=(const float*)d_in[3],  *bl1=(const float*)d_in[4];
    const float *Wr1=(const float*)d_in[5],  *br1=(const float*)d_in[6];
    const float *att1=(const float*)d_in[7], *b1=(const float*)d_in[8];
    const float *Wl2=(const float*)d_in[9],  *bl2=(const float*)d_in[10];
    const float *Wr2=(const float*)d_in[11], *br2=(const float*)d_in[12];
    const float *att2=(const float*)d_in[13],*b2=(const float*)d_in[14];
    const float *Wl3=(const float*)d_in[15], *bl3=(const float*)d_in[16];
    const float *Wr3=(const float*)d_in[17], *br3=(const float*)d_in[18];
    const float *att3=(const float*)d_in[19],*b3=(const float*)d_in[20];

    float *p_xl, *p_xr, *p_h;
    cudaGetSymbolAddress((void**)&p_xl, g_xl);
    cudaGetSymbolAddress((void**)&p_xr, g_xr);
    cudaGetSymbolAddress((void**)&p_h,  g_h);

    static cudaStream_t s2 = nullptr;
    static cudaEvent_t evFork = nullptr, evJoin = nullptr;
    if (s2 == nullptr) {
        cudaStreamCreateWithFlags(&s2, cudaStreamNonBlocking);
        cudaEventCreateWithFlags(&evFork, cudaEventDisableTiming);
        cudaEventCreateWithFlags(&evJoin, cudaEventDisableTiming);
    }

    const int gNodeWarp = gridFor((long long)NN * 32);
    const int gLin128   = (NN + 63) / 64;
    const int gLinTf    = (NN + 63) / 64;
    const int gLin32    = (NN + 255) / 256;
    const int gPool     = (NN + 255) / 256;

    // ---- fork: layer-1 linear + pool_init on s2, concurrent with CSR build
    cudaEventRecord(evFork, 0);
    cudaStreamWaitEvent(s2, evFork, 0);
    linear_dual_kernel<8, 128><<<gLin128, 256, 0, s2>>>(x, Wl1, bl1, Wr1, br1,
                                                        p_xl, p_xr);
    pool_init_kernel<<<gridFor(NG * 32), TB, 0, s2>>>();
    cudaEventRecord(evJoin, s2);

    // ---- CSR (dst-indexed) build on default stream -------------------------
    deg_count_kernel<<<gridFor(NE), TB>>>(ei);
    scanA_kernel<<<NSCAN, 256>>>();
    scanB_kernel<<<1, 256>>>();
    scanC_kernel<<<NSCAN, 256>>>();
    fill_kernel<<<gridFor(ET), TB>>>(ei);

    cudaStreamWaitEvent(0, evJoin, 0);

    // ---- layer 1: 8 -> 128 (H=2, C=64)
    gat_fused128_kernel<<<gNodeWarp, TB>>>(att1, b1, p_h);

    // ---- layer 2: 128 -> 128 (H=2, C=64), TF32 tensor GEMM
    linear_tf32_dual_kernel<<<gLinTf, 256>>>(p_h, Wl2, bl2, Wr2, br2, p_xl, p_xr);
    gat_fused128_kernel<<<gNodeWarp, TB>>>(att2, b2, p_h);

    // ---- layer 3: 128 -> 32 (H=1, C=32)
    linear_dual_kernel<128, 32><<<gLin32, 256>>>(p_h, Wl3, bl3, Wr3, br3, p_xl, p_xr);
    gat_fused32_kernel<<<gNodeWarp, TB>>>(att3, b3, p_h);

    // ---- pooling
    pool_accum_kernel<<<gPool, 256>>>(p_h, batch);
    pool_final_kernel<<<gridFor(NG * 64), TB>>>((float*)d_out);
}

// round 16
// speedup vs baseline: 1.5522x; 1.0158x over previous
#include <cuda_runtime.h>
#include <math.h>

// GATv2 x3 + pooling: multi-block CSR scan + offset-softmax fused edge pass,
// TF32 mma.sync dual linears (128->128 and 128->32), stream-forked layer-1
// linear + pool_init overlapped with CSR build, SMEM pooling.
namespace {
constexpr int NN = 50000;
constexpr int NE = 800000;
constexpr int ET = NE + NN;
constexpr int NG = 16;
constexpr int TB = 256;
constexpr int NSCAN = (NN + 255) / 256;
}

// ---------------- scratch ---------------------------------------------------
__device__ __align__(16) float g_xl[(size_t)NN * 128];
__device__ __align__(16) float g_xr[(size_t)NN * 128];
__device__ __align__(16) float g_h[(size_t)NN * 128];
__device__ int g_deg[NN];
__device__ int g_rowptr[NN + 1];
__device__ int g_cur[NN];
__device__ int g_csrc[ET];
__device__ int g_bsum[256];
__device__ int g_boff[256];
__device__ float g_psum[NG * 32];
__device__ float g_pmax[NG * 32];
__device__ float g_cntf[NG];

__device__ __forceinline__ void atomicMaxF(float* a, float v) {
    if (v >= 0.f) atomicMax((int*)a, __float_as_int(v));
    else          atomicMin((unsigned int*)a, __float_as_uint(v));
}

__device__ __forceinline__ unsigned f2tf32(float x) {
    unsigned u;
    asm("cvt.rna.tf32.f32 %0, %1;" : "=r"(u) : "f"(x));
    return u;
}

// ---------------- CSR build -------------------------------------------------
__global__ void deg_count_kernel(const int* __restrict__ ei) {
    int e = blockIdx.x * blockDim.x + threadIdx.x;
    if (e < NE) atomicAdd(&g_deg[ei[NE + e]], 1);
}
__global__ void scanA_kernel() {
    __shared__ int sh[256];
    const int tid = threadIdx.x;
    const int node = blockIdx.x * 256 + tid;
    sh[tid] = (node < NN) ? g_deg[node] + 1 : 0;
    __syncthreads();
#pragma unroll
    for (int off = 128; off > 0; off >>= 1) {
        if (tid < off) sh[tid] += sh[tid + off];
        __syncthreads();
    }
    if (tid == 0) g_bsum[blockIdx.x] = sh[0];
}
__global__ void scanB_kernel() {
    __shared__ int sh[256];
    const int tid = threadIdx.x;
    sh[tid] = (tid < NSCAN) ? g_bsum[tid] : 0;
    __syncthreads();
#pragma unroll
    for (int off = 1; off < 256; off <<= 1) {
        int add = (tid >= off) ? sh[tid - off] : 0;
        __syncthreads();
        sh[tid] += add;
        __syncthreads();
    }
    g_boff[tid] = (tid == 0) ? 0 : sh[tid - 1];
    if (tid == 0) g_rowptr[NN] = ET;
}
__global__ void scanC_kernel() {
    __shared__ int sh[256];
    const int tid = threadIdx.x;
    const int node = blockIdx.x * 256 + tid;
    const int val = (node < NN) ? g_deg[node] + 1 : 0;
    sh[tid] = val;
    __syncthreads();
#pragma unroll
    for (int off = 1; off < 256; off <<= 1) {
        int add = (tid >= off) ? sh[tid - off] : 0;
        __syncthreads();
        sh[tid] += add;
        __syncthreads();
    }
    if (node < NN) {
        const int pos = g_boff[blockIdx.x] + sh[tid] - val;
        g_rowptr[node] = pos;
        g_cur[node] = pos;
    }
}
__global__ void fill_kernel(const int* __restrict__ ei) {
    int e = blockIdx.x * blockDim.x + threadIdx.x;
    if (e < NN) g_deg[e] = 0;
    if (e >= ET) return;
    int src, dst;
    if (e < NE) { src = ei[e]; dst = ei[NE + e]; }
    else        { src = e - NE; dst = src; }
    int pos = atomicAdd(&g_cur[dst], 1);
    g_csrc[pos] = src;
}

// ---------------- TF32 mma dual linear: 128 -> OUTC x 2 matrices -------------
template<int OUTC>
__global__ __launch_bounds__(256)
void linear_tf32_dual_kernel(const float* __restrict__ X,
                             const float* __restrict__ Wl, const float* __restrict__ Bl,
                             const float* __restrict__ Wr, const float* __restrict__ Br,
                             float* __restrict__ Yl, float* __restrict__ Yr) {
    constexpr int NT = OUTC / 8;                 // n-tiles of 8
    __shared__ unsigned Ws[2][8][OUTC + 8];
    const int tid  = threadIdx.x;
    const int warp = tid >> 5, lane = tid & 31;
    const int mat  = warp & 1;
    const int rt   = warp >> 1;
    const int node0 = blockIdx.x * 64 + rt * 16;
    const int gid = lane >> 2;
    const int tig = lane & 3;

    float acc[NT][4];
#pragma unroll
    for (int nt = 0; nt < NT; nt++)
#pragma unroll
        for (int j = 0; j < 4; j++) acc[nt][j] = 0.f;

    const int rA0 = min(node0 + gid, NN - 1);
    const int rA1 = min(node0 + gid + 8, NN - 1);

    for (int kc = 0; kc < 16; kc++) {
        __syncthreads();
        for (int i = tid; i < 2 * 8 * OUTC; i += 256) {
            const int m   = i / (8 * OUTC);
            const int rem = i % (8 * OUTC);
            const int k   = rem / OUTC;
            const int n   = rem % OUTC;
            const float* Wp = m ? Wr : Wl;
            Ws[m][k][n] = f2tf32(Wp[(size_t)(kc * 8 + k) * OUTC + n]);
        }
        __syncthreads();

        const int c0 = kc * 8 + tig;
        const unsigned a0 = f2tf32(X[(size_t)rA0 * 128 + c0]);
        const unsigned a1 = f2tf32(X[(size_t)rA1 * 128 + c0]);
        const unsigned a2 = f2tf32(X[(size_t)rA0 * 128 + c0 + 4]);
        const unsigned a3 = f2tf32(X[(size_t)rA1 * 128 + c0 + 4]);

#pragma unroll
        for (int nt = 0; nt < NT; nt++) {
            const unsigned b0 = Ws[mat][tig][nt * 8 + gid];
            const unsigned b1 = Ws[mat][tig + 4][nt * 8 + gid];
            asm volatile(
                "mma.sync.aligned.m16n8k8.row.col.f32.tf32.tf32.f32 "
                "{%0,%1,%2,%3}, {%4,%5,%6,%7}, {%8,%9}, {%0,%1,%2,%3};"
                : "+f"(acc[nt][0]), "+f"(acc[nt][1]),
                  "+f"(acc[nt][2]), "+f"(acc[nt][3])
                : "r"(a0), "r"(a1), "r"(a2), "r"(a3), "r"(b0), "r"(b1));
        }
    }

    const float* Bp = mat ? Br : Bl;
    float* Yp = mat ? Yr : Yl;
    const int row0 = node0 + gid;
    const int row1 = row0 + 8;
#pragma unroll
    for (int nt = 0; nt < NT; nt++) {
        const int col = nt * 8 + tig * 2;
        const float b0v = Bp[col], b1v = Bp[col + 1];
        if (row0 < NN) {
            Yp[(size_t)row0 * OUTC + col]     = acc[nt][0] + b0v;
            Yp[(size_t)row0 * OUTC + col + 1] = acc[nt][1] + b1v;
        }
        if (row1 < NN) {
            Yp[(size_t)row1 * OUTC + col]     = acc[nt][2] + b0v;
            Yp[(size_t)row1 * OUTC + col + 1] = acc[nt][3] + b1v;
        }
    }
}

// ---------------- dual linear (fp32): used for 8 -> 128 ---------------------
template<int IN, int OUT>
__global__ __launch_bounds__(256)
void linear_dual_kernel(const float* __restrict__ X,
                        const float* __restrict__ Wl, const float* __restrict__ Bl,
                        const float* __restrict__ Wr, const float* __restrict__ Br,
                        float* __restrict__ Yl, float* __restrict__ Yr) {
    constexpr int TO  = OUT / 8;
    constexpr int NGR = 256 / TO;
    constexpr int NPB = NGR * 4;
    constexpr int KT  = (IN < 32) ? IN : 32;

    __shared__ float Xs[KT][NPB + 4];
    __shared__ float Wsl[KT][OUT];
    __shared__ float Wsr[KT][OUT];

    const int tid = threadIdx.x;
    const int og  = tid % TO;
    const int ng  = tid / TO;
    const int nb  = blockIdx.x * NPB;

    float accl[4][8], accr[4][8];
#pragma unroll
    for (int i = 0; i < 4; i++)
#pragma unroll
        for (int j = 0; j < 8; j++) { accl[i][j] = 0.f; accr[i][j] = 0.f; }

    for (int kt = 0; kt < IN; kt += KT) {
        __syncthreads();
        for (int idx = tid; idx < KT * OUT / 4; idx += 256) {
            const int k = idx / (OUT / 4), o4 = idx % (OUT / 4);
            ((float4*)Wsl[k])[o4] = ((const float4*)(Wl + (size_t)(kt + k) * OUT))[o4];
            ((float4*)Wsr[k])[o4] = ((const float4*)(Wr + (size_t)(kt + k) * OUT))[o4];
        }
        for (int idx = tid; idx < NPB * (KT / 4); idx += 256) {
            const int ni = idx / (KT / 4), f4 = idx % (KT / 4);
            const int gn = nb + ni;
            float4 xv = make_float4(0.f, 0.f, 0.f, 0.f);
            if (gn < NN)
                xv = ((const float4*)(X + (size_t)gn * IN + kt))[f4];
            Xs[f4 * 4 + 0][ni] = xv.x;
            Xs[f4 * 4 + 1][ni] = xv.y;
            Xs[f4 * 4 + 2][ni] = xv.z;
            Xs[f4 * 4 + 3][ni] = xv.w;
        }
        __syncthreads();
#pragma unroll
        for (int k = 0; k < KT; k++) {
            float xv[4];
#pragma unroll
            for (int i = 0; i < 4; i++) xv[i] = Xs[k][ng * 4 + i];
            const float4 wl0 = ((const float4*)&Wsl[k][og * 8])[0];
            const float4 wl1 = ((const float4*)&Wsl[k][og * 8])[1];
            const float4 wr0 = ((const float4*)&Wsr[k][og * 8])[0];
            const float4 wr1 = ((const float4*)&Wsr[k][og * 8])[1];
#pragma unroll
            for (int i = 0; i < 4; i++) {
                accl[i][0] += xv[i] * wl0.x; accl[i][1] += xv[i] * wl0.y;
                accl[i][2] += xv[i] * wl0.z; accl[i][3] += xv[i] * wl0.w;
                accl[i][4] += xv[i] * wl1.x; accl[i][5] += xv[i] * wl1.y;
                accl[i][6] += xv[i] * wl1.z; accl[i][7] += xv[i] * wl1.w;
                accr[i][0] += xv[i] * wr0.x; accr[i][1] += xv[i] * wr0.y;
                accr[i][2] += xv[i] * wr0.z; accr[i][3] += xv[i] * wr0.w;
                accr[i][4] += xv[i] * wr1.x; accr[i][5] += xv[i] * wr1.y;
                accr[i][6] += xv[i] * wr1.z; accr[i][7] += xv[i] * wr1.w;
            }
        }
    }

    const float4 bl0 = ((const float4*)(Bl + og * 8))[0];
    const float4 bl1 = ((const float4*)(Bl + og * 8))[1];
    const float4 br0 = ((const float4*)(Br + og * 8))[0];
    const float4 br1 = ((const float4*)(Br + og * 8))[1];
#pragma unroll
    for (int i = 0; i < 4; i++) {
        const int node = nb + ng * 4 + i;
        if (node >= NN) continue;
        float4 o;
        o = make_float4(accl[i][0]+bl0.x, accl[i][1]+bl0.y, accl[i][2]+bl0.z, accl[i][3]+bl0.w);
        ((float4*)(Yl + (size_t)node * OUT + og * 8))[0] = o;
        o = make_float4(accl[i][4]+bl1.x, accl[i][5]+bl1.y, accl[i][6]+bl1.z, accl[i][7]+bl1.w);
        ((float4*)(Yl + (size_t)node * OUT + og * 8))[1] = o;
        o = make_float4(accr[i][0]+br0.x, accr[i][1]+br0.y, accr[i][2]+br0.z, accr[i][3]+br0.w);
        ((float4*)(Yr + (size_t)node * OUT + og * 8))[0] = o;
        o = make_float4(accr[i][4]+br1.x, accr[i][5]+br1.y, accr[i][6]+br1.z, accr[i][7]+br1.w);
        ((float4*)(Yr + (size_t)node * OUT + og * 8))[1] = o;
    }
}

// ---------------- fused GATv2 edge pass (CT=128, H=2), warp/dst, ILP4 -------
__global__ void gat_fused128_kernel(const float* __restrict__ att,
                                    const float* __restrict__ B,
                                    float* __restrict__ out) {
    const int node = (blockIdx.x * blockDim.x + threadIdx.x) >> 5;
    if (node >= NN) return;
    const int lane = threadIdx.x & 31;

    const float4 xrv  = *(const float4*)(g_xr + (size_t)node * 128 + lane * 4);
    const float4 attv = *(const float4*)(att + lane * 4);

    float s_self;
    {
        const float4 xlv = *(const float4*)(g_xl + (size_t)node * 128 + lane * 4);
        float t, sc = 0.f;
        t = xlv.x + xrv.x; t = t > 0.f ? t : 0.2f * t; sc += t * attv.x;
        t = xlv.y + xrv.y; t = t > 0.f ? t : 0.2f * t; sc += t * attv.y;
        t = xlv.z + xrv.z; t = t > 0.f ? t : 0.2f * t; sc += t * attv.z;
        t = xlv.w + xrv.w; t = t > 0.f ? t : 0.2f * t; sc += t * attv.w;
#pragma unroll
        for (int off = 1; off <= 8; off <<= 1)
            sc += __shfl_xor_sync(0xffffffffu, sc, off);
        s_self = sc;
    }

    int p  = g_rowptr[node];
    const int pe = g_rowptr[node + 1];

    float  dd[4] = {0.f, 0.f, 0.f, 0.f};
    float4 A[4];
#pragma unroll
    for (int j = 0; j < 4; j++) A[j] = make_float4(0.f, 0.f, 0.f, 0.f);

    for (; p + 3 < pe; p += 4) {
        int s[4];
#pragma unroll
        for (int j = 0; j < 4; j++) s[j] = g_csrc[p + j];
        float4 a[4];
#pragma unroll
        for (int j = 0; j < 4; j++)
            a[j] = *(const float4*)(g_xl + (size_t)s[j] * 128 + lane * 4);

        float pp[4];
#pragma unroll
        for (int j = 0; j < 4; j++) {
            float t, sc = 0.f;
            t = a[j].x + xrv.x; t = t > 0.f ? t : 0.2f * t; sc += t * attv.x;
            t = a[j].y + xrv.y; t = t > 0.f ? t : 0.2f * t; sc += t * attv.y;
            t = a[j].z + xrv.z; t = t > 0.f ? t : 0.2f * t; sc += t * attv.z;
            t = a[j].w + xrv.w; t = t > 0.f ? t : 0.2f * t; sc += t * attv.w;
            pp[j] = sc;
        }
#pragma unroll
        for (int off = 1; off <= 8; off <<= 1)
#pragma unroll
            for (int j = 0; j < 4; j++)
                pp[j] += __shfl_xor_sync(0xffffffffu, pp[j], off);
#pragma unroll
        for (int j = 0; j < 4; j++) {
            const float w = __expf(pp[j] - s_self);
            dd[j] += w;
            A[j].x += w * a[j].x;
            A[j].y += w * a[j].y;
            A[j].z += w * a[j].z;
            A[j].w += w * a[j].w;
        }
    }
    for (; p < pe; ++p) {
        const int s0 = g_csrc[p];
        const float4 a0 = *(const float4*)(g_xl + (size_t)s0 * 128 + lane * 4);
        float t, p0 = 0.f;
        t = a0.x + xrv.x; t = t > 0.f ? t : 0.2f * t; p0 += t * attv.x;
        t = a0.y + xrv.y; t = t > 0.f ? t : 0.2f * t; p0 += t * attv.y;
        t = a0.z + xrv.z; t = t > 0.f ? t : 0.2f * t; p0 += t * attv.z;
        t = a0.w + xrv.w; t = t > 0.f ? t : 0.2f * t; p0 += t * attv.w;
#pragma unroll
        for (int off = 1; off <= 8; off <<= 1)
            p0 += __shfl_xor_sync(0xffffffffu, p0, off);
        const float w = __expf(p0 - s_self);
        dd[0] += w;
        A[0].x += w * a0.x;
        A[0].y += w * a0.y;
        A[0].z += w * a0.z;
        A[0].w += w * a0.w;
    }

    const float d = dd[0] + dd[1] + dd[2] + dd[3];
    float4 acc;
    acc.x = A[0].x + A[1].x + A[2].x + A[3].x;
    acc.y = A[0].y + A[1].y + A[2].y + A[3].y;
    acc.z = A[0].z + A[1].z + A[2].z + A[3].z;
    acc.w = A[0].w + A[1].w + A[2].w + A[3].w;

    const float inv = 1.f / d;
    const float4 bv = *(const float4*)(B + lane * 4);
    float4 o;
    o.x = acc.x * inv + bv.x; o.x = o.x > 0.f ? o.x : expm1f(o.x);
    o.y = acc.y * inv + bv.y; o.y = o.y > 0.f ? o.y : expm1f(o.y);
    o.z = acc.z * inv + bv.z; o.z = o.z > 0.f ? o.z : expm1f(o.z);
    o.w = acc.w * inv + bv.w; o.w = o.w > 0.f ? o.w : expm1f(o.w);
    *(float4*)(out + (size_t)node * 128 + lane * 4) = o;
}

// ---------------- fused GATv2 edge pass (CT=32, H=1), warp/dst, ILP8 --------
__global__ void gat_fused32_kernel(const float* __restrict__ att,
                                   const float* __restrict__ B,
                                   float* __restrict__ out) {
    const int node = (blockIdx.x * blockDim.x + threadIdx.x) >> 5;
    if (node >= NN) return;
    const int lane = threadIdx.x & 31;

    const float xrv  = g_xr[(size_t)node * 32 + lane];
    const float attv = att[lane];

    float s_self;
    {
        const float xlv = g_xl[(size_t)node * 32 + lane];
        float t = xlv + xrv; t = t > 0.f ? t : 0.2f * t;
        float sc = t * attv;
#pragma unroll
        for (int off = 1; off <= 16; off <<= 1)
            sc += __shfl_xor_sync(0xffffffffu, sc, off);
        s_self = sc;
    }

    int p  = g_rowptr[node];
    const int pe = g_rowptr[node + 1];

    float dd0 = 0.f, dd1 = 0.f, A0 = 0.f, A1 = 0.f;

    for (; p + 7 < pe; p += 8) {
        float a[8], pp[8];
#pragma unroll
        for (int j = 0; j < 8; j++) {
            const int s = g_csrc[p + j];
            a[j] = g_xl[(size_t)s * 32 + lane];
            float t = a[j] + xrv; t = t > 0.f ? t : 0.2f * t;
            pp[j] = t * attv;
        }
#pragma unroll
        for (int off = 1; off <= 16; off <<= 1)
#pragma unroll
            for (int j = 0; j < 8; j++)
                pp[j] += __shfl_xor_sync(0xffffffffu, pp[j], off);
#pragma unroll
        for (int j = 0; j < 8; j += 2) {
            const float w0 = __expf(pp[j]     - s_self);
            const float w1 = __expf(pp[j + 1] - s_self);
            dd0 += w0; A0 += w0 * a[j];
            dd1 += w1; A1 += w1 * a[j + 1];
        }
    }
    for (; p < pe; ++p) {
        const int s = g_csrc[p];
        const float a0 = g_xl[(size_t)s * 32 + lane];
        float t = a0 + xrv; t = t > 0.f ? t : 0.2f * t;
        float p0 = t * attv;
#pragma unroll
        for (int off = 1; off <= 16; off <<= 1)
            p0 += __shfl_xor_sync(0xffffffffu, p0, off);
        const float w = __expf(p0 - s_self);
        dd0 += w; A0 += w * a0;
    }

    float o = (A0 + A1) / (dd0 + dd1) + B[lane];
    o = o > 0.f ? o : expm1f(o);
    out[(size_t)node * 32 + lane] = o;
}

// ---------------- pooling ----------------------------------------------------
__global__ void pool_init_kernel() {
    int i = blockIdx.x * blockDim.x + threadIdx.x;
    if (i < NG * 32) { g_psum[i] = 0.f; g_pmax[i] = -INFINITY; }
    if (i < NG) g_cntf[i] = 0.f;
}

__global__ __launch_bounds__(256)
void pool_accum_kernel(const float* __restrict__ h,
                       const int* __restrict__ batch) {
    __shared__ float ssum[NG * 32];
    __shared__ float smax[NG * 32];
    __shared__ int   scnt[NG];
    const int tid = threadIdx.x;
    for (int i = tid; i < NG * 32; i += 256) { ssum[i] = 0.f; smax[i] = -INFINITY; }
    if (tid < NG) scnt[tid] = 0;
    __syncthreads();

    const int warp = tid >> 5, lane = tid & 31;
    const int nbase = blockIdx.x * 256 + warp * 32;
#pragma unroll 4
    for (int i = 0; i < 32; i++) {
        const int node = nbase + i;
        if (node >= NN) break;
        const int g = batch[node];
        const float v = h[(size_t)node * 32 + lane];
        atomicAdd(&ssum[g * 32 + lane], v);
        atomicMaxF(&smax[g * 32 + lane], v);
        if (lane == 0) atomicAdd(&scnt[g], 1);
    }
    __syncthreads();

    for (int i = tid; i < NG * 32; i += 256) {
        if (ssum[i] != 0.f) atomicAdd(&g_psum[i], ssum[i]);
        if (smax[i] != -INFINITY) atomicMaxF(&g_pmax[i], smax[i]);
    }
    if (tid < NG && scnt[tid] > 0) atomicAdd(&g_cntf[tid], (float)scnt[tid]);
}

__global__ void pool_final_kernel(float* __restrict__ out) {
    const int i = blockIdx.x * blockDim.x + threadIdx.x;
    if (i >= NG * 64) return;
    const int g = i / 64, c = i % 64;
    out[i] = (c < 32) ? g_psum[g * 32 + c] / g_cntf[g]
                      : g_pmax[g * 32 + (c - 32)];
}

// ---------------- launch ------------------------------------------------------
static inline int gridFor(long long n) { return (int)((n + TB - 1) / TB); }

extern "C" void kernel_launch(void* const* d_in, const int* in_sizes, int n_in,
                              void* d_out, int out_size) {
    const float* x     = (const float*)d_in[0];
    const int*   ei    = (const int*)d_in[1];
    const int*   batch = (const int*)d_in[2];
    const float *Wl1=(const float*)d_in[3],  *bl1=(const float*)d_in[4];
    const float *Wr1=(const float*)d_in[5],  *br1=(const float*)d_in[6];
    const float *att1=(const float*)d_in[7], *b1=(const float*)d_in[8];
    const float *Wl2=(const float*)d_in[9],  *bl2=(const float*)d_in[10];
    const float *Wr2=(const float*)d_in[11], *br2=(const float*)d_in[12];
    const float *att2=(const float*)d_in[13],*b2=(const float*)d_in[14];
    const float *Wl3=(const float*)d_in[15], *bl3=(const float*)d_in[16];
    const float *Wr3=(const float*)d_in[17], *br3=(const float*)d_in[18];
    const float *att3=(const float*)d_in[19],*b3=(const float*)d_in[20];

    float *p_xl, *p_xr, *p_h;
    cudaGetSymbolAddress((void**)&p_xl, g_xl);
    cudaGetSymbolAddress((void**)&p_xr, g_xr);
    cudaGetSymbolAddress((void**)&p_h,  g_h);

    static cudaStream_t s2 = nullptr;
    static cudaEvent_t evFork = nullptr, evJoin = nullptr;
    if (s2 == nullptr) {
        cudaStreamCreateWithFlags(&s2, cudaStreamNonBlocking);
        cudaEventCreateWithFlags(&evFork, cudaEventDisableTiming);
        cudaEventCreateWithFlags(&evJoin, cudaEventDisableTiming);
    }

    const int gNodeWarp = gridFor((long long)NN * 32);
    const int gLin128   = (NN + 63) / 64;
    const int gLinTf    = (NN + 63) / 64;
    const int gPool     = (NN + 255) / 256;

    // ---- fork: layer-1 linear + pool_init on s2, concurrent with CSR build
    cudaEventRecord(evFork, 0);
    cudaStreamWaitEvent(s2, evFork, 0);
    linear_dual_kernel<8, 128><<<gLin128, 256, 0, s2>>>(x, Wl1, bl1, Wr1, br1,
                                                        p_xl, p_xr);
    pool_init_kernel<<<gridFor(NG * 32), TB, 0, s2>>>();
    cudaEventRecord(evJoin, s2);

    // ---- CSR (dst-indexed) build on default stream -------------------------
    deg_count_kernel<<<gridFor(NE), TB>>>(ei);
    scanA_kernel<<<NSCAN, 256>>>();
    scanB_kernel<<<1, 256>>>();
    scanC_kernel<<<NSCAN, 256>>>();
    fill_kernel<<<gridFor(ET), TB>>>(ei);

    cudaStreamWaitEvent(0, evJoin, 0);

    // ---- layer 1: 8 -> 128 (H=2, C=64)
    gat_fused128_kernel<<<gNodeWarp, TB>>>(att1, b1, p_h);

    // ---- layer 2: 128 -> 128 (H=2, C=64), TF32 tensor GEMM
    linear_tf32_dual_kernel<128><<<gLinTf, 256>>>(p_h, Wl2, bl2, Wr2, br2, p_xl, p_xr);
    gat_fused128_kernel<<<gNodeWarp, TB>>>(att2, b2, p_h);

    // ---- layer 3: 128 -> 32 (H=1, C=32), TF32 tensor GEMM
    linear_tf32_dual_kernel<32><<<gLinTf, 256>>>(p_h, Wl3, bl3, Wr3, br3, p_xl, p_xr);
    gat_fused32_kernel<<<gNodeWarp, TB>>>(att3, b3, p_h);

    // ---- pooling
    pool_accum_kernel<<<gPool, 256>>>(p_h, batch);
    pool_final_kernel<<<gridFor(NG * 64), TB>>>((float*)d_out);
}

// round 17
// speedup vs baseline: 1.5653x; 1.0084x over previous
#include <cuda_runtime.h>
#include <math.h>

// GATv2 x3 + pooling: multi-block CSR scan (B fused into C) + offset-softmax
// fused edge pass (fmax-form LeakyReLU), TF32 mma.sync dual linears,
// stream-forked layer-1 linear + pool_init, SMEM pooling.
namespace {
constexpr int NN = 50000;
constexpr int NE = 800000;
constexpr int ET = NE + NN;
constexpr int NG = 16;
constexpr int TB = 256;
constexpr int NSCAN = (NN + 255) / 256;
}

// ---------------- scratch ---------------------------------------------------
__device__ __align__(16) float g_xl[(size_t)NN * 128];
__device__ __align__(16) float g_xr[(size_t)NN * 128];
__device__ __align__(16) float g_h[(size_t)NN * 128];
__device__ int g_deg[NN];
__device__ int g_rowptr[NN + 1];
__device__ int g_cur[NN];
__device__ int g_csrc[ET];
__device__ int g_bsum[256];
__device__ float g_psum[NG * 32];
__device__ float g_pmax[NG * 32];
__device__ float g_cntf[NG];

__device__ __forceinline__ void atomicMaxF(float* a, float v) {
    if (v >= 0.f) atomicMax((int*)a, __float_as_int(v));
    else          atomicMin((unsigned int*)a, __float_as_uint(v));
}

__device__ __forceinline__ unsigned f2tf32(float x) {
    unsigned u;
    asm("cvt.rna.tf32.f32 %0, %1;" : "=r"(u) : "f"(x));
    return u;
}

// leaky_relu(t) = max(t, 0.2t): identical for all finite t, 2 instrs
__device__ __forceinline__ float lrelu(float t) { return fmaxf(t, 0.2f * t); }

// ---------------- CSR build -------------------------------------------------
__global__ void deg_count_kernel(const int* __restrict__ ei) {
    int e = blockIdx.x * blockDim.x + threadIdx.x;
    if (e < NE) atomicAdd(&g_deg[ei[NE + e]], 1);
}
__global__ void scanA_kernel() {
    __shared__ int sh[256];
    const int tid = threadIdx.x;
    const int node = blockIdx.x * 256 + tid;
    sh[tid] = (node < NN) ? g_deg[node] + 1 : 0;
    __syncthreads();
#pragma unroll
    for (int off = 128; off > 0; off >>= 1) {
        if (tid < off) sh[tid] += sh[tid + off];
        __syncthreads();
    }
    if (tid == 0) {
        g_bsum[blockIdx.x] = sh[0];
        if (blockIdx.x == 0) g_rowptr[NN] = ET;
    }
}
// scanC with embedded block-sum scan (redundant per block; removes scanB)
__global__ void scanC_kernel() {
    __shared__ int bs[256];
    __shared__ int sh[256];
    const int tid = threadIdx.x;
    bs[tid] = (tid < NSCAN) ? g_bsum[tid] : 0;
    const int node = blockIdx.x * 256 + tid;
    const int val = (node < NN) ? g_deg[node] + 1 : 0;
    sh[tid] = val;
    __syncthreads();
#pragma unroll
    for (int off = 1; off < 256; off <<= 1) {
        int addb = (tid >= off) ? bs[tid - off] : 0;
        int adds = (tid >= off) ? sh[tid - off] : 0;
        __syncthreads();
        bs[tid] += addb;
        sh[tid] += adds;
        __syncthreads();
    }
    if (node < NN) {
        const int boff = (blockIdx.x == 0) ? 0 : bs[blockIdx.x - 1];
        const int pos = boff + sh[tid] - val;
        g_rowptr[node] = pos;
        g_cur[node] = pos;
    }
}
__global__ void fill_kernel(const int* __restrict__ ei) {
    int e = blockIdx.x * blockDim.x + threadIdx.x;
    if (e < NN) g_deg[e] = 0;
    if (e >= ET) return;
    int src, dst;
    if (e < NE) { src = ei[e]; dst = ei[NE + e]; }
    else        { src = e - NE; dst = src; }
    int pos = atomicAdd(&g_cur[dst], 1);
    g_csrc[pos] = src;
}

// ---------------- TF32 mma dual linear: 128 -> OUTC x 2 matrices -------------
template<int OUTC>
__global__ __launch_bounds__(256)
void linear_tf32_dual_kernel(const float* __restrict__ X,
                             const float* __restrict__ Wl, const float* __restrict__ Bl,
                             const float* __restrict__ Wr, const float* __restrict__ Br,
                             float* __restrict__ Yl, float* __restrict__ Yr) {
    constexpr int NT = OUTC / 8;
    __shared__ unsigned Ws[2][8][OUTC + 8];
    const int tid  = threadIdx.x;
    const int warp = tid >> 5, lane = tid & 31;
    const int mat  = warp & 1;
    const int rt   = warp >> 1;
    const int node0 = blockIdx.x * 64 + rt * 16;
    const int gid = lane >> 2;
    const int tig = lane & 3;

    float acc[NT][4];
#pragma unroll
    for (int nt = 0; nt < NT; nt++)
#pragma unroll
        for (int j = 0; j < 4; j++) acc[nt][j] = 0.f;

    const int rA0 = min(node0 + gid, NN - 1);
    const int rA1 = min(node0 + gid + 8, NN - 1);

    for (int kc = 0; kc < 16; kc++) {
        __syncthreads();
        for (int i = tid; i < 2 * 8 * OUTC; i += 256) {
            const int m   = i / (8 * OUTC);
            const int rem = i % (8 * OUTC);
            const int k   = rem / OUTC;
            const int n   = rem % OUTC;
            const float* Wp = m ? Wr : Wl;
            Ws[m][k][n] = f2tf32(Wp[(size_t)(kc * 8 + k) * OUTC + n]);
        }
        __syncthreads();

        const int c0 = kc * 8 + tig;
        const unsigned a0 = f2tf32(X[(size_t)rA0 * 128 + c0]);
        const unsigned a1 = f2tf32(X[(size_t)rA1 * 128 + c0]);
        const unsigned a2 = f2tf32(X[(size_t)rA0 * 128 + c0 + 4]);
        const unsigned a3 = f2tf32(X[(size_t)rA1 * 128 + c0 + 4]);

#pragma unroll
        for (int nt = 0; nt < NT; nt++) {
            const unsigned b0 = Ws[mat][tig][nt * 8 + gid];
            const unsigned b1 = Ws[mat][tig + 4][nt * 8 + gid];
            asm volatile(
                "mma.sync.aligned.m16n8k8.row.col.f32.tf32.tf32.f32 "
                "{%0,%1,%2,%3}, {%4,%5,%6,%7}, {%8,%9}, {%0,%1,%2,%3};"
                : "+f"(acc[nt][0]), "+f"(acc[nt][1]),
                  "+f"(acc[nt][2]), "+f"(acc[nt][3])
                : "r"(a0), "r"(a1), "r"(a2), "r"(a3), "r"(b0), "r"(b1));
        }
    }

    const float* Bp = mat ? Br : Bl;
    float* Yp = mat ? Yr : Yl;
    const int row0 = node0 + gid;
    const int row1 = row0 + 8;
#pragma unroll
    for (int nt = 0; nt < NT; nt++) {
        const int col = nt * 8 + tig * 2;
        const float b0v = Bp[col], b1v = Bp[col + 1];
        if (row0 < NN) {
            Yp[(size_t)row0 * OUTC + col]     = acc[nt][0] + b0v;
            Yp[(size_t)row0 * OUTC + col + 1] = acc[nt][1] + b1v;
        }
        if (row1 < NN) {
            Yp[(size_t)row1 * OUTC + col]     = acc[nt][2] + b0v;
            Yp[(size_t)row1 * OUTC + col + 1] = acc[nt][3] + b1v;
        }
    }
}

// ---------------- dual linear (fp32): used for 8 -> 128 ---------------------
template<int IN, int OUT>
__global__ __launch_bounds__(256)
void linear_dual_kernel(const float* __restrict__ X,
                        const float* __restrict__ Wl, const float* __restrict__ Bl,
                        const float* __restrict__ Wr, const float* __restrict__ Br,
                        float* __restrict__ Yl, float* __restrict__ Yr) {
    constexpr int TO  = OUT / 8;
    constexpr int NGR = 256 / TO;
    constexpr int NPB = NGR * 4;
    constexpr int KT  = (IN < 32) ? IN : 32;

    __shared__ float Xs[KT][NPB + 4];
    __shared__ float Wsl[KT][OUT];
    __shared__ float Wsr[KT][OUT];

    const int tid = threadIdx.x;
    const int og  = tid % TO;
    const int ng  = tid / TO;
    const int nb  = blockIdx.x * NPB;

    float accl[4][8], accr[4][8];
#pragma unroll
    for (int i = 0; i < 4; i++)
#pragma unroll
        for (int j = 0; j < 8; j++) { accl[i][j] = 0.f; accr[i][j] = 0.f; }

    for (int kt = 0; kt < IN; kt += KT) {
        __syncthreads();
        for (int idx = tid; idx < KT * OUT / 4; idx += 256) {
            const int k = idx / (OUT / 4), o4 = idx % (OUT / 4);
            ((float4*)Wsl[k])[o4] = ((const float4*)(Wl + (size_t)(kt + k) * OUT))[o4];
            ((float4*)Wsr[k])[o4] = ((const float4*)(Wr + (size_t)(kt + k) * OUT))[o4];
        }
        for (int idx = tid; idx < NPB * (KT / 4); idx += 256) {
            const int ni = idx / (KT / 4), f4 = idx % (KT / 4);
            const int gn = nb + ni;
            float4 xv = make_float4(0.f, 0.f, 0.f, 0.f);
            if (gn < NN)
                xv = ((const float4*)(X + (size_t)gn * IN + kt))[f4];
            Xs[f4 * 4 + 0][ni] = xv.x;
            Xs[f4 * 4 + 1][ni] = xv.y;
            Xs[f4 * 4 + 2][ni] = xv.z;
            Xs[f4 * 4 + 3][ni] = xv.w;
        }
        __syncthreads();
#pragma unroll
        for (int k = 0; k < KT; k++) {
            float xv[4];
#pragma unroll
            for (int i = 0; i < 4; i++) xv[i] = Xs[k][ng * 4 + i];
            const float4 wl0 = ((const float4*)&Wsl[k][og * 8])[0];
            const float4 wl1 = ((const float4*)&Wsl[k][og * 8])[1];
            const float4 wr0 = ((const float4*)&Wsr[k][og * 8])[0];
            const float4 wr1 = ((const float4*)&Wsr[k][og * 8])[1];
#pragma unroll
            for (int i = 0; i < 4; i++) {
                accl[i][0] += xv[i] * wl0.x; accl[i][1] += xv[i] * wl0.y;
                accl[i][2] += xv[i] * wl0.z; accl[i][3] += xv[i] * wl0.w;
                accl[i][4] += xv[i] * wl1.x; accl[i][5] += xv[i] * wl1.y;
                accl[i][6] += xv[i] * wl1.z; accl[i][7] += xv[i] * wl1.w;
                accr[i][0] += xv[i] * wr0.x; accr[i][1] += xv[i] * wr0.y;
                accr[i][2] += xv[i] * wr0.z; accr[i][3] += xv[i] * wr0.w;
                accr[i][4] += xv[i] * wr1.x; accr[i][5] += xv[i] * wr1.y;
                accr[i][6] += xv[i] * wr1.z; accr[i][7] += xv[i] * wr1.w;
            }
        }
    }

    const float4 bl0 = ((const float4*)(Bl + og * 8))[0];
    const float4 bl1 = ((const float4*)(Bl + og * 8))[1];
    const float4 br0 = ((const float4*)(Br + og * 8))[0];
    const float4 br1 = ((const float4*)(Br + og * 8))[1];
#pragma unroll
    for (int i = 0; i < 4; i++) {
        const int node = nb + ng * 4 + i;
        if (node >= NN) continue;
        float4 o;
        o = make_float4(accl[i][0]+bl0.x, accl[i][1]+bl0.y, accl[i][2]+bl0.z, accl[i][3]+bl0.w);
        ((float4*)(Yl + (size_t)node * OUT + og * 8))[0] = o;
        o = make_float4(accl[i][4]+bl1.x, accl[i][5]+bl1.y, accl[i][6]+bl1.z, accl[i][7]+bl1.w);
        ((float4*)(Yl + (size_t)node * OUT + og * 8))[1] = o;
        o = make_float4(accr[i][0]+br0.x, accr[i][1]+br0.y, accr[i][2]+br0.z, accr[i][3]+br0.w);
        ((float4*)(Yr + (size_t)node * OUT + og * 8))[0] = o;
        o = make_float4(accr[i][4]+br1.x, accr[i][5]+br1.y, accr[i][6]+br1.z, accr[i][7]+br1.w);
        ((float4*)(Yr + (size_t)node * OUT + og * 8))[1] = o;
    }
}

// ---------------- fused GATv2 edge pass (CT=128, H=2), warp/dst, ILP4 -------
__global__ void gat_fused128_kernel(const float* __restrict__ att,
                                    const float* __restrict__ B,
                                    float* __restrict__ out) {
    const int node = (blockIdx.x * blockDim.x + threadIdx.x) >> 5;
    if (node >= NN) return;
    const int lane = threadIdx.x & 31;

    const float4 xrv  = *(const float4*)(g_xr + (size_t)node * 128 + lane * 4);
    const float4 attv = *(const float4*)(att + lane * 4);

    float s_self;
    {
        const float4 xlv = *(const float4*)(g_xl + (size_t)node * 128 + lane * 4);
        float sc = 0.f;
        sc += lrelu(xlv.x + xrv.x) * attv.x;
        sc += lrelu(xlv.y + xrv.y) * attv.y;
        sc += lrelu(xlv.z + xrv.z) * attv.z;
        sc += lrelu(xlv.w + xrv.w) * attv.w;
#pragma unroll
        for (int off = 1; off <= 8; off <<= 1)
            sc += __shfl_xor_sync(0xffffffffu, sc, off);
        s_self = sc;
    }

    int p  = g_rowptr[node];
    const int pe = g_rowptr[node + 1];

    float  dd[4] = {0.f, 0.f, 0.f, 0.f};
    float4 A[4];
#pragma unroll
    for (int j = 0; j < 4; j++) A[j] = make_float4(0.f, 0.f, 0.f, 0.f);

    for (; p + 3 < pe; p += 4) {
        int s[4];
#pragma unroll
        for (int j = 0; j < 4; j++) s[j] = g_csrc[p + j];
        float4 a[4];
#pragma unroll
        for (int j = 0; j < 4; j++)
            a[j] = *(const float4*)(g_xl + (size_t)s[j] * 128 + lane * 4);

        float pp[4];
#pragma unroll
        for (int j = 0; j < 4; j++) {
            float sc = 0.f;
            sc += lrelu(a[j].x + xrv.x) * attv.x;
            sc += lrelu(a[j].y + xrv.y) * attv.y;
            sc += lrelu(a[j].z + xrv.z) * attv.z;
            sc += lrelu(a[j].w + xrv.w) * attv.w;
            pp[j] = sc;
        }
#pragma unroll
        for (int off = 1; off <= 8; off <<= 1)
#pragma unroll
            for (int j = 0; j < 4; j++)
                pp[j] += __shfl_xor_sync(0xffffffffu, pp[j], off);
#pragma unroll
        for (int j = 0; j < 4; j++) {
            const float w = __expf(pp[j] - s_self);
            dd[j] += w;
            A[j].x += w * a[j].x;
            A[j].y += w * a[j].y;
            A[j].z += w * a[j].z;
            A[j].w += w * a[j].w;
        }
    }
    for (; p < pe; ++p) {
        const int s0 = g_csrc[p];
        const float4 a0 = *(const float4*)(g_xl + (size_t)s0 * 128 + lane * 4);
        float p0 = 0.f;
        p0 += lrelu(a0.x + xrv.x) * attv.x;
        p0 += lrelu(a0.y + xrv.y) * attv.y;
        p0 += lrelu(a0.z + xrv.z) * attv.z;
        p0 += lrelu(a0.w + xrv.w) * attv.w;
#pragma unroll
        for (int off = 1; off <= 8; off <<= 1)
            p0 += __shfl_xor_sync(0xffffffffu, p0, off);
        const float w = __expf(p0 - s_self);
        dd[0] += w;
        A[0].x += w * a0.x;
        A[0].y += w * a0.y;
        A[0].z += w * a0.z;
        A[0].w += w * a0.w;
    }

    const float d = dd[0] + dd[1] + dd[2] + dd[3];
    float4 acc;
    acc.x = A[0].x + A[1].x + A[2].x + A[3].x;
    acc.y = A[0].y + A[1].y + A[2].y + A[3].y;
    acc.z = A[0].z + A[1].z + A[2].z + A[3].z;
    acc.w = A[0].w + A[1].w + A[2].w + A[3].w;

    const float inv = 1.f / d;
    const float4 bv = *(const float4*)(B + lane * 4);
    float4 o;
    o.x = acc.x * inv + bv.x; o.x = o.x > 0.f ? o.x : expm1f(o.x);
    o.y = acc.y * inv + bv.y; o.y = o.y > 0.f ? o.y : expm1f(o.y);
    o.z = acc.z * inv + bv.z; o.z = o.z > 0.f ? o.z : expm1f(o.z);
    o.w = acc.w * inv + bv.w; o.w = o.w > 0.f ? o.w : expm1f(o.w);
    *(float4*)(out + (size_t)node * 128 + lane * 4) = o;
}

// ---------------- fused GATv2 edge pass (CT=32, H=1), warp/dst, ILP8 --------
__global__ void gat_fused32_kernel(const float* __restrict__ att,
                                   const float* __restrict__ B,
                                   float* __restrict__ out) {
    const int node = (blockIdx.x * blockDim.x + threadIdx.x) >> 5;
    if (node >= NN) return;
    const int lane = threadIdx.x & 31;

    const float xrv  = g_xr[(size_t)node * 32 + lane];
    const float attv = att[lane];

    float s_self;
    {
        const float xlv = g_xl[(size_t)node * 32 + lane];
        float sc = lrelu(xlv + xrv) * attv;
#pragma unroll
        for (int off = 1; off <= 16; off <<= 1)
            sc += __shfl_xor_sync(0xffffffffu, sc, off);
        s_self = sc;
    }

    int p  = g_rowptr[node];
    const int pe = g_rowptr[node + 1];

    float dd0 = 0.f, dd1 = 0.f, A0 = 0.f, A1 = 0.f;

    for (; p + 7 < pe; p += 8) {
        float a[8], pp[8];
#pragma unroll
        for (int j = 0; j < 8; j++) {
            const int s = g_csrc[p + j];
            a[j] = g_xl[(size_t)s * 32 + lane];
            pp[j] = lrelu(a[j] + xrv) * attv;
        }
#pragma unroll
        for (int off = 1; off <= 16; off <<= 1)
#pragma unroll
            for (int j = 0; j < 8; j++)
                pp[j] += __shfl_xor_sync(0xffffffffu, pp[j], off);
#pragma unroll
        for (int j = 0; j < 8; j += 2) {
            const float w0 = __expf(pp[j]     - s_self);
            const float w1 = __expf(pp[j + 1] - s_self);
            dd0 += w0; A0 += w0 * a[j];
            dd1 += w1; A1 += w1 * a[j + 1];
        }
    }
    for (; p < pe; ++p) {
        const int s = g_csrc[p];
        const float a0 = g_xl[(size_t)s * 32 + lane];
        float p0 = lrelu(a0 + xrv) * attv;
#pragma unroll
        for (int off = 1; off <= 16; off <<= 1)
            p0 += __shfl_xor_sync(0xffffffffu, p0, off);
        const float w = __expf(p0 - s_self);
        dd0 += w; A0 += w * a0;
    }

    float o = (A0 + A1) / (dd0 + dd1) + B[lane];
    o = o > 0.f ? o : expm1f(o);
    out[(size_t)node * 32 + lane] = o;
}

// ---------------- pooling ----------------------------------------------------
__global__ void pool_init_kernel() {
    int i = blockIdx.x * blockDim.x + threadIdx.x;
    if (i < NG * 32) { g_psum[i] = 0.f; g_pmax[i] = -INFINITY; }
    if (i < NG) g_cntf[i] = 0.f;
}

__global__ __launch_bounds__(256)
void pool_accum_kernel(const float* __restrict__ h,
                       const int* __restrict__ batch) {
    __shared__ float ssum[NG * 32];
    __shared__ float smax[NG * 32];
    __shared__ int   scnt[NG];
    const int tid = threadIdx.x;
    for (int i = tid; i < NG * 32; i += 256) { ssum[i] = 0.f; smax[i] = -INFINITY; }
    if (tid < NG) scnt[tid] = 0;
    __syncthreads();

    const int warp = tid >> 5, lane = tid & 31;
    const int nbase = blockIdx.x * 256 + warp * 32;
#pragma unroll 4
    for (int i = 0; i < 32; i++) {
        const int node = nbase + i;
        if (node >= NN) break;
        const int g = batch[node];
        const float v = h[(size_t)node * 32 + lane];
        atomicAdd(&ssum[g * 32 + lane], v);
        atomicMaxF(&smax[g * 32 + lane], v);
        if (lane == 0) atomicAdd(&scnt[g], 1);
    }
    __syncthreads();

    for (int i = tid; i < NG * 32; i += 256) {
        if (ssum[i] != 0.f) atomicAdd(&g_psum[i], ssum[i]);
        if (smax[i] != -INFINITY) atomicMaxF(&g_pmax[i], smax[i]);
    }
    if (tid < NG && scnt[tid] > 0) atomicAdd(&g_cntf[tid], (float)scnt[tid]);
}

__global__ void pool_final_kernel(float* __restrict__ out) {
    const int i = blockIdx.x * blockDim.x + threadIdx.x;
    if (i >= NG * 64) return;
    const int g = i / 64, c = i % 64;
    out[i] = (c < 32) ? g_psum[g * 32 + c] / g_cntf[g]
                      : g_pmax[g * 32 + (c - 32)];
}

// ---------------- launch ------------------------------------------------------
static inline int gridFor(long long n) { return (int)((n + TB - 1) / TB); }

extern "C" void kernel_launch(void* const* d_in, const int* in_sizes, int n_in,
                              void* d_out, int out_size) {
    const float* x     = (const float*)d_in[0];
    const int*   ei    = (const int*)d_in[1];
    const int*   batch = (const int*)d_in[2];
    const float *Wl1=(const float*)d_in[3],  *bl1=(const float*)d_in[4];
    const float *Wr1=(const float*)d_in[5],  *br1=(const float*)d_in[6];
    const float *att1=(const float*)d_in[7], *b1=(const float*)d_in[8];
    const float *Wl2=(const float*)d_in[9],  *bl2=(const float*)d_in[10];
    const float *Wr2=(const float*)d_in[11], *br2=(const float*)d_in[12];
    const float *att2=(const float*)d_in[13],*b2=(const float*)d_in[14];
    const float *Wl3=(const float*)d_in[15], *bl3=(const float*)d_in[16];
    const float *Wr3=(const float*)d_in[17], *br3=(const float*)d_in[18];
    const float *att3=(const float*)d_in[19],*b3=(const float*)d_in[20];

    float *p_xl, *p_xr, *p_h;
    cudaGetSymbolAddress((void**)&p_xl, g_xl);
    cudaGetSymbolAddress((void**)&p_xr, g_xr);
    cudaGetSymbolAddress((void**)&p_h,  g_h);

    static cudaStream_t s2 = nullptr;
    static cudaEvent_t evFork = nullptr, evJoin = nullptr;
    if (s2 == nullptr) {
        cudaStreamCreateWithFlags(&s2, cudaStreamNonBlocking);
        cudaEventCreateWithFlags(&evFork, cudaEventDisableTiming);
        cudaEventCreateWithFlags(&evJoin, cudaEventDisableTiming);
    }

    const int gNodeWarp = gridFor((long long)NN * 32);
    const int gLin128   = (NN + 63) / 64;
    const int gLinTf    = (NN + 63) / 64;
    const int gPool     = (NN + 255) / 256;

    // ---- fork: layer-1 linear + pool_init on s2, concurrent with CSR build
    cudaEventRecord(evFork, 0);
    cudaStreamWaitEvent(s2, evFork, 0);
    linear_dual_kernel<8, 128><<<gLin128, 256, 0, s2>>>(x, Wl1, bl1, Wr1, br1,
                                                        p_xl, p_xr);
    pool_init_kernel<<<gridFor(NG * 32), TB, 0, s2>>>();
    cudaEventRecord(evJoin, s2);

    // ---- CSR (dst-indexed) build on default stream -------------------------
    deg_count_kernel<<<gridFor(NE), TB>>>(ei);
    scanA_kernel<<<NSCAN, 256>>>();
    scanC_kernel<<<NSCAN, 256>>>();
    fill_kernel<<<gridFor(ET), TB>>>(ei);

    cudaStreamWaitEvent(0, evJoin, 0);

    // ---- layer 1: 8 -> 128 (H=2, C=64)
    gat_fused128_kernel<<<gNodeWarp, TB>>>(att1, b1, p_h);

    // ---- layer 2: 128 -> 128 (H=2, C=64), TF32 tensor GEMM
    linear_tf32_dual_kernel<128><<<gLinTf, 256>>>(p_h, Wl2, bl2, Wr2, br2, p_xl, p_xr);
    gat_fused128_kernel<<<gNodeWarp, TB>>>(att2, b2, p_h);

    // ---- layer 3: 128 -> 32 (H=1, C=32), TF32 tensor GEMM
    linear_tf32_dual_kernel<32><<<gLinTf, 256>>>(p_h, Wl3, bl3, Wr3, br3, p_xl, p_xr);
    gat_fused32_kernel<<<gNodeWarp, TB>>>(att3, b3, p_h);

    // ---- pooling
    pool_accum_kernel<<<gPool, 256>>>(p_h, batch);
    pool_final_kernel<<<gridFor(NG * 64), TB>>>((float*)d_out);
}